// round 1
// baseline (speedup 1.0000x reference)
#include <cuda_runtime.h>
#include <cuda_bf16.h>
#include <math.h>

// ---------------- problem constants ----------------
#define HH 50
#define WW 50
#define NPOS 2500          // H*W
#define DIM 256
#define HEADS 8
#define DH 64
#define G 4
#define INNER 512          // HEADS*DH
#define OFFD 128           // INNER/G
#define CPB 64             // DIM/4
#define O 2                // HEADS/G
#define KS 6
#define DF 4
#define PAD 1
#define HK 12
#define JJ 144             // HK*HK
#define SCALE 0.125f
#define OFF_SCALE 4.0f
#define SEQ 2501           // H*W+1

// ---------------- scratch (device globals, no allocation) ----------------
__device__ float g_q[INNER * NPOS];          // q = wq @ f1         (512 x 2500)
__device__ float g_off1[INNER * JJ];         // gelu(depthwise conv) (4*128 x 144)
__device__ float g_vgs[G * JJ * 2];          // normalized sample grid
__device__ float g_kv[DIM * JJ];             // sampled features     (256 x 144)
__device__ float g_k[INNER * JJ];            // k                   (512 x 144)
__device__ float g_v[INNER * JJ];            // v                   (512 x 144)
__device__ float g_bias[HEADS * NPOS * JJ];  // CPB bias per head   (8 x 2500 x 144)
__device__ float g_ao[INNER * NPOS];         // attention output    (512 x 2500)

// ---------------- generic tiled SGEMM ----------------
// C[m, n] = sum_k A[m,k] * B[k*ldb + boff + n]  (+ bias[m]), stored C[m*ldc + coff + n]
__global__ void sgemm64(const float* __restrict__ A, const float* __restrict__ B,
                        float* __restrict__ C, int M, int N, int K,
                        int ldb, int boff, int ldc, int coff,
                        const float* __restrict__ bias) {
    __shared__ float As[16][64 + 1];
    __shared__ float Bs[16][64 + 1];
    const int tx = threadIdx.x & 15;   // n dir
    const int ty = threadIdx.x >> 4;   // m dir
    const int m0 = blockIdx.y * 64;
    const int n0 = blockIdx.x * 64;
    float acc[4][4];
#pragma unroll
    for (int u = 0; u < 4; u++)
#pragma unroll
        for (int w = 0; w < 4; w++) acc[u][w] = 0.f;

    for (int k0 = 0; k0 < K; k0 += 16) {
        for (int t = threadIdx.x; t < 64 * 16; t += 256) {
            int m = t >> 4, k = t & 15;
            float v = 0.f;
            if (m0 + m < M) v = A[(size_t)(m0 + m) * K + k0 + k];
            As[k][m] = v;
        }
        for (int t = threadIdx.x; t < 64 * 16; t += 256) {
            int k = t >> 6, n = t & 63;
            float v = 0.f;
            if (n0 + n < N) v = B[(size_t)(k0 + k) * ldb + boff + n0 + n];
            Bs[k][n] = v;
        }
        __syncthreads();
#pragma unroll
        for (int k = 0; k < 16; k++) {
            float a[4], b[4];
#pragma unroll
            for (int u = 0; u < 4; u++) a[u] = As[k][ty * 4 + u];
#pragma unroll
            for (int w = 0; w < 4; w++) b[w] = Bs[k][tx * 4 + w];
#pragma unroll
            for (int u = 0; u < 4; u++)
#pragma unroll
                for (int w = 0; w < 4; w++) acc[u][w] += a[u] * b[w];
        }
        __syncthreads();
    }
#pragma unroll
    for (int u = 0; u < 4; u++) {
        int m = m0 + ty * 4 + u;
        if (m >= M) continue;
        float bb = bias ? bias[m] : 0.f;
#pragma unroll
        for (int w = 0; w < 4; w++) {
            int n = n0 + tx * 4 + w;
            if (n < N) C[(size_t)m * ldc + coff + n] = acc[u][w] + bb;
        }
    }
}

// ---------------- depthwise conv (stride 4, pad 1, 6x6) + bias + exact GELU ----------------
// input: g_q viewed as (4, 128, 50, 50); output g_off1 (4,128,12,12)
__global__ void dconv_kernel(const float* __restrict__ w1, const float* __restrict__ b1) {
    const int gc = blockIdx.x;          // 0..511  (g*128 + c)
    const int c = gc & 127;
    const int j = threadIdx.x;          // 0..143
    const int oy = j / HK, ox = j % HK;
    const float* qrow = &g_q[(size_t)gc * NPOS];
    const float* wt = &w1[c * 36];
    float acc = 0.f;
#pragma unroll
    for (int ky = 0; ky < KS; ky++) {
        int iy = oy * DF - PAD + ky;
        if (iy < 0 || iy >= HH) continue;
#pragma unroll
        for (int kx = 0; kx < KS; kx++) {
            int ix = ox * DF - PAD + kx;
            if (ix < 0 || ix >= WW) continue;
            acc += qrow[iy * WW + ix] * wt[ky * KS + kx];
        }
    }
    float x = acc + b1[c];
    // exact gelu
    float gl = 0.5f * x * (1.0f + erff(x * 0.70710678118654752f));
    g_off1[(size_t)gc * JJ + j] = gl;
}

// ---------------- 1x1 conv + tanh*4 + build normalized sampling grid ----------------
__global__ void offgrid_kernel(const float* __restrict__ w2) {
    const int g = blockIdx.x;   // 0..3
    const int j = threadIdx.x;  // 0..143
    float s0 = 0.f, s1 = 0.f;
    for (int c = 0; c < OFFD; c++) {
        float v = g_off1[(size_t)(g * OFFD + c) * JJ + j];
        s0 += w2[c] * v;            // w_off2[0, c]
        s1 += w2[OFFD + c] * v;     // w_off2[1, c]
    }
    float offx = tanhf(s0) * OFF_SCALE;
    float offy = tanhf(s1) * OFF_SCALE;
    int x = j % HK, y = j / HK;
    float vx = (float)x + offx;
    float vy = (float)y + offy;
    float sx = 2.0f * vx / (float)(HK - 1) - 1.0f;
    float sy = 2.0f * vy / (float)(HK - 1) - 1.0f;
    g_vgs[(g * JJ + j) * 2 + 0] = sx;
    g_vgs[(g * JJ + j) * 2 + 1] = sy;
}

// ---------------- bilinear grid sample of f2 ----------------
// blocks: g*144 + j ; threads: c in 0..63 (channel within group)
__global__ void gsample_kernel(const float* __restrict__ x2) {
    const int blk = blockIdx.x;
    const int g = blk / JJ;
    const int j = blk % JJ;
    const int c = threadIdx.x;     // 0..63
    float sx = g_vgs[(g * JJ + j) * 2 + 0];
    float sy = g_vgs[(g * JJ + j) * 2 + 1];
    float x = (sx + 1.0f) * (WW * 0.5f) - 0.5f;
    float y = (sy + 1.0f) * (HH * 0.5f) - 0.5f;
    float x0f = floorf(x), y0f = floorf(y);
    int x0 = (int)x0f, y0 = (int)y0f;
    float wx1 = x - x0f, wy1 = y - y0f;
    float wx0 = 1.0f - wx1, wy0 = 1.0f - wy1;
    const float* img = &x2[(size_t)(g * (DIM / G) + c) * SEQ + 1];  // (50,50), row-major
    float acc = 0.f;
#pragma unroll
    for (int dy = 0; dy < 2; dy++) {
#pragma unroll
        for (int dx = 0; dx < 2; dx++) {
            int ix = x0 + dx, iy = y0 + dy;
            float w = (dx ? wx1 : wx0) * (dy ? wy1 : wy0);
            if (ix >= 0 && ix < WW && iy >= 0 && iy < HH)
                acc += img[iy * WW + ix] * w;
        }
    }
    g_kv[(size_t)(g * (DIM / G) + c) * JJ + j] = acc;
}

// ---------------- CPB bias MLP: 2 -> 64 -> relu -> 64 -> relu -> 2 ----------------
// one thread per (g, i, j) point; writes g_bias[h=g*2+o][i][j]
__global__ void cpb_kernel(const float* __restrict__ W1, const float* __restrict__ B1,
                           const float* __restrict__ W2, const float* __restrict__ B2,
                           const float* __restrict__ W3, const float* __restrict__ B3) {
    __shared__ float W2s[64 * 64];    // transposed: W2s[k*64+m] = W2[m*64+k]
    __shared__ float W1s[2 * 64];
    __shared__ float B1s[64];
    __shared__ float B2s[64];
    __shared__ float W3s[64 * 2];
    for (int t = threadIdx.x; t < 4096; t += blockDim.x) {
        int m = t >> 6, k = t & 63;
        W2s[k * 64 + m] = W2[t];
    }
    for (int t = threadIdx.x; t < 128; t += blockDim.x) W1s[t] = W1[t];
    for (int t = threadIdx.x; t < 64; t += blockDim.x) { B1s[t] = B1[t]; B2s[t] = B2[t]; }
    for (int t = threadIdx.x; t < 128; t += blockDim.x) W3s[t] = W3[t];
    __syncthreads();

    const int p = blockIdx.x * blockDim.x + threadIdx.x;
    if (p >= G * NPOS * JJ) return;
    const int g = p / (NPOS * JJ);
    const int r = p % (NPOS * JJ);
    const int i = r / JJ;
    const int j = r % JJ;
    const int ix = i % WW, iy = i / WW;

    float gqx = 2.0f * (float)ix / (float)(WW - 1) - 1.0f;
    float gqy = 2.0f * (float)iy / (float)(HH - 1) - 1.0f;
    float px = gqx - g_vgs[(g * JJ + j) * 2 + 0];
    float py = gqy - g_vgs[(g * JJ + j) * 2 + 1];
    float fx = copysignf(log1pf(fabsf(px)), px);
    float fy = copysignf(log1pf(fabsf(py)), py);

    float h1[64];
#pragma unroll
    for (int m = 0; m < 64; m++)
        h1[m] = fmaxf(fx * W1s[m] + fy * W1s[64 + m] + B1s[m], 0.f);

    float a0 = B3[0], a1 = B3[1];
    for (int k = 0; k < 64; k++) {
        float h2 = B2s[k];
        const float4* w2r = reinterpret_cast<const float4*>(&W2s[k * 64]);
#pragma unroll
        for (int m4 = 0; m4 < 16; m4++) {
            float4 wv = w2r[m4];
            h2 += h1[4 * m4 + 0] * wv.x + h1[4 * m4 + 1] * wv.y +
                  h1[4 * m4 + 2] * wv.z + h1[4 * m4 + 3] * wv.w;
        }
        float rr = fmaxf(h2, 0.f);
        a0 += rr * W3s[k * 2 + 0];
        a1 += rr * W3s[k * 2 + 1];
    }
    size_t base = ((size_t)(g * 2) * NPOS + i) * JJ + j;
    g_bias[base] = a0;
    g_bias[base + (size_t)NPOS * JJ] = a1;   // head g*2+1
}

// ---------------- fused sim + bias + softmax + out ----------------
// block: (h = blockIdx.y, i-tile of 8 = blockIdx.x), 256 threads = 8 warps
__global__ void attn_kernel() {
    const int h = blockIdx.y;
    const int i0 = blockIdx.x * 8;
    __shared__ float qs[8][64];
    __shared__ float ps[8][JJ];
    __shared__ float rsum[8];
    const int tid = threadIdx.x;

    for (int t = tid; t < 8 * 64; t += 256) {
        int r = t >> 6, d = t & 63;
        int i = i0 + r;
        qs[r][d] = (i < NPOS) ? g_q[(size_t)(h * 64 + d) * NPOS + i] * SCALE : 0.f;
    }
    __syncthreads();

    for (int t = tid; t < 8 * JJ; t += 256) {
        int r = t / JJ, j = t % JJ;
        int i = i0 + r;
        float s = 0.f;
#pragma unroll 8
        for (int d = 0; d < 64; d++)
            s += qs[r][d] * g_k[(size_t)(h * 64 + d) * JJ + j];
        if (i < NPOS) s += g_bias[((size_t)h * NPOS + i) * JJ + j];
        ps[r][j] = s;
    }
    __syncthreads();

    // softmax: warp w owns row w
    const int w = tid >> 5, lane = tid & 31;
    {
        float m = -1e30f;
        for (int j = lane; j < JJ; j += 32) m = fmaxf(m, ps[w][j]);
#pragma unroll
        for (int o = 16; o; o >>= 1) m = fmaxf(m, __shfl_xor_sync(0xffffffffu, m, o));
        float s = 0.f;
        for (int j = lane; j < JJ; j += 32) {
            float e = expf(ps[w][j] - m);
            ps[w][j] = e;
            s += e;
        }
#pragma unroll
        for (int o = 16; o; o >>= 1) s += __shfl_xor_sync(0xffffffffu, s, o);
        if (lane == 0) rsum[w] = s;
    }
    __syncthreads();

    for (int t = tid; t < 8 * 64; t += 256) {
        int r = t >> 6, d = t & 63;
        int i = i0 + r;
        if (i >= NPOS) continue;
        const float* vrow = &g_v[(size_t)(h * 64 + d) * JJ];
        float o = 0.f;
#pragma unroll 8
        for (int j = 0; j < JJ; j++) o += ps[r][j] * vrow[j];
        g_ao[(size_t)(h * 64 + d) * NPOS + i] = o / rsum[r];
    }
}

// ---------------- cls passthrough ----------------
__global__ void cls_kernel(const float* __restrict__ x1, float* __restrict__ out) {
    int o = threadIdx.x;   // 256 threads
    out[(size_t)o * SEQ] = x1[(size_t)o * SEQ];
}

// ---------------- launcher ----------------
extern "C" void kernel_launch(void* const* d_in, const int* in_sizes, int n_in,
                              void* d_out, int out_size) {
    const float* x1    = (const float*)d_in[0];
    const float* x2    = (const float*)d_in[1];
    const float* w_off1= (const float*)d_in[2];
    const float* b_off1= (const float*)d_in[3];
    const float* w_off2= (const float*)d_in[4];
    const float* wq    = (const float*)d_in[5];
    const float* wk    = (const float*)d_in[6];
    const float* wv    = (const float*)d_in[7];
    const float* wout  = (const float*)d_in[8];
    const float* bout  = (const float*)d_in[9];
    const float* cpb_w1= (const float*)d_in[10];
    const float* cpb_b1= (const float*)d_in[11];
    const float* cpb_w2= (const float*)d_in[12];
    const float* cpb_b2= (const float*)d_in[13];
    const float* cpb_w3= (const float*)d_in[14];
    const float* cpb_b3= (const float*)d_in[15];
    float* out = (float*)d_out;

    float *qp, *kvp, *kp, *vp, *aop;
    cudaGetSymbolAddress((void**)&qp,  g_q);
    cudaGetSymbolAddress((void**)&kvp, g_kv);
    cudaGetSymbolAddress((void**)&kp,  g_k);
    cudaGetSymbolAddress((void**)&vp,  g_v);
    cudaGetSymbolAddress((void**)&aop, g_ao);

    // 1) q = wq @ f1   (512 x 2500, K=256); f1[k][n] = x1[k*2501 + 1 + n]
    sgemm64<<<dim3(40, 8), 256>>>(wq, x1, qp, INNER, NPOS, DIM, SEQ, 1, NPOS, 0, nullptr);

    // 2) depthwise conv + gelu
    dconv_kernel<<<INNER, JJ>>>(w_off1, b_off1);

    // 3) 1x1 conv + tanh + grid
    offgrid_kernel<<<G, JJ>>>(w_off2);

    // 4) bilinear sample
    gsample_kernel<<<G * JJ, 64>>>(x2);

    // 5) k, v GEMMs (512 x 144, K=256)
    sgemm64<<<dim3(3, 8), 256>>>(wk, kvp, kp, INNER, JJ, DIM, JJ, 0, JJ, 0, nullptr);
    sgemm64<<<dim3(3, 8), 256>>>(wv, kvp, vp, INNER, JJ, DIM, JJ, 0, JJ, 0, nullptr);

    // 6) CPB bias MLP (the FLOP monster)
    cpb_kernel<<<(G * NPOS * JJ + 127) / 128, 128>>>(cpb_w1, cpb_b1, cpb_w2, cpb_b2,
                                                     cpb_w3, cpb_b3);

    // 7) attention: sim + bias + softmax + out
    attn_kernel<<<dim3((NPOS + 7) / 8, HEADS), 256>>>();

    // 8) wout @ attn_out + bout -> output columns 1..2500
    sgemm64<<<dim3(40, 4), 256>>>(wout, aop, out, DIM, NPOS, INNER, NPOS, 0, SEQ, 1, bout);

    // 9) cls token passthrough -> column 0
    cls_kernel<<<1, DIM>>>(x1, out);
}

// round 4
// speedup vs baseline: 1.3991x; 1.3991x over previous
#include <cuda_runtime.h>
#include <cuda_bf16.h>
#include <math.h>
#include <stdint.h>

// ---------------- problem constants ----------------
#define HH 50
#define WW 50
#define NPOS 2500          // H*W
#define DIM 256
#define HEADS 8
#define DH 64
#define G 4
#define INNER 512          // HEADS*DH
#define OFFD 128           // INNER/G
#define CPB 64             // DIM/4
#define O 2                // HEADS/G
#define KS 6
#define DF 4
#define PAD 1
#define HK 12
#define JJ 144             // HK*HK
#define SCALE 0.125f
#define OFF_SCALE 4.0f
#define SEQ 2501           // H*W+1
#define PTS_TOTAL (G * NPOS * JJ)   // 1,440,000
#define PTS_PER_G (NPOS * JJ)       // 360,000

// ---------------- scratch (device globals, no allocation) ----------------
__device__ float g_q[INNER * NPOS];          // q = wq @ f1         (512 x 2500)
__device__ float g_off1[INNER * JJ];         // gelu(depthwise conv) (4*128 x 144)
__device__ float g_vgs[G * JJ * 2];          // normalized sample grid
__device__ float g_kv[DIM * JJ];             // sampled features     (256 x 144)
__device__ float g_k[INNER * JJ];            // k                   (512 x 144)
__device__ float g_v[INNER * JJ];            // v                   (512 x 144)
__device__ float g_bias[HEADS * NPOS * JJ];  // CPB bias per head   (8 x 2500 x 144)
__device__ float g_ao[INNER * NPOS];         // attention output    (512 x 2500)

// ---------------- generic tiled SGEMM ----------------
__global__ void sgemm64(const float* __restrict__ A, const float* __restrict__ B,
                        float* __restrict__ C, int M, int N, int K,
                        int ldb, int boff, int ldc, int coff,
                        const float* __restrict__ bias) {
    __shared__ float As[16][64 + 1];
    __shared__ float Bs[16][64 + 1];
    const int tx = threadIdx.x & 15;   // n dir
    const int ty = threadIdx.x >> 4;   // m dir
    const int m0 = blockIdx.y * 64;
    const int n0 = blockIdx.x * 64;
    float acc[4][4];
#pragma unroll
    for (int u = 0; u < 4; u++)
#pragma unroll
        for (int w = 0; w < 4; w++) acc[u][w] = 0.f;

    for (int k0 = 0; k0 < K; k0 += 16) {
        for (int t = threadIdx.x; t < 64 * 16; t += 256) {
            int m = t >> 4, k = t & 15;
            float v = 0.f;
            if (m0 + m < M) v = A[(size_t)(m0 + m) * K + k0 + k];
            As[k][m] = v;
        }
        for (int t = threadIdx.x; t < 64 * 16; t += 256) {
            int k = t >> 6, n = t & 63;
            float v = 0.f;
            if (n0 + n < N) v = B[(size_t)(k0 + k) * ldb + boff + n0 + n];
            Bs[k][n] = v;
        }
        __syncthreads();
#pragma unroll
        for (int k = 0; k < 16; k++) {
            float a[4], b[4];
#pragma unroll
            for (int u = 0; u < 4; u++) a[u] = As[k][ty * 4 + u];
#pragma unroll
            for (int w = 0; w < 4; w++) b[w] = Bs[k][tx * 4 + w];
#pragma unroll
            for (int u = 0; u < 4; u++)
#pragma unroll
                for (int w = 0; w < 4; w++) acc[u][w] += a[u] * b[w];
        }
        __syncthreads();
    }
#pragma unroll
    for (int u = 0; u < 4; u++) {
        int m = m0 + ty * 4 + u;
        if (m >= M) continue;
        float bb = bias ? bias[m] : 0.f;
#pragma unroll
        for (int w = 0; w < 4; w++) {
            int n = n0 + tx * 4 + w;
            if (n < N) C[(size_t)m * ldc + coff + n] = acc[u][w] + bb;
        }
    }
}

// ---------------- depthwise conv (stride 4, pad 1, 6x6) + bias + exact GELU ----------------
__global__ void dconv_kernel(const float* __restrict__ w1, const float* __restrict__ b1) {
    const int gc = blockIdx.x;          // 0..511  (g*128 + c)
    const int c = gc & 127;
    const int j = threadIdx.x;          // 0..143
    const int oy = j / HK, ox = j % HK;
    const float* qrow = &g_q[(size_t)gc * NPOS];
    const float* wt = &w1[c * 36];
    float acc = 0.f;
#pragma unroll
    for (int ky = 0; ky < KS; ky++) {
        int iy = oy * DF - PAD + ky;
        if (iy < 0 || iy >= HH) continue;
#pragma unroll
        for (int kx = 0; kx < KS; kx++) {
            int ix = ox * DF - PAD + kx;
            if (ix < 0 || ix >= WW) continue;
            acc += qrow[iy * WW + ix] * wt[ky * KS + kx];
        }
    }
    float x = acc + b1[c];
    float gl = 0.5f * x * (1.0f + erff(x * 0.70710678118654752f));
    g_off1[(size_t)gc * JJ + j] = gl;
}

// ---------------- 1x1 conv + tanh*4 + build normalized sampling grid ----------------
__global__ void offgrid_kernel(const float* __restrict__ w2) {
    const int g = blockIdx.x;   // 0..3
    const int j = threadIdx.x;  // 0..143
    float s0 = 0.f, s1 = 0.f;
    for (int c = 0; c < OFFD; c++) {
        float v = g_off1[(size_t)(g * OFFD + c) * JJ + j];
        s0 += w2[c] * v;
        s1 += w2[OFFD + c] * v;
    }
    float offx = tanhf(s0) * OFF_SCALE;
    float offy = tanhf(s1) * OFF_SCALE;
    int x = j % HK, y = j / HK;
    float vx = (float)x + offx;
    float vy = (float)y + offy;
    float sx = 2.0f * vx / (float)(HK - 1) - 1.0f;
    float sy = 2.0f * vy / (float)(HK - 1) - 1.0f;
    g_vgs[(g * JJ + j) * 2 + 0] = sx;
    g_vgs[(g * JJ + j) * 2 + 1] = sy;
}

// ---------------- bilinear grid sample of f2 ----------------
__global__ void gsample_kernel(const float* __restrict__ x2) {
    const int blk = blockIdx.x;
    const int g = blk / JJ;
    const int j = blk % JJ;
    const int c = threadIdx.x;     // 0..63
    float sx = g_vgs[(g * JJ + j) * 2 + 0];
    float sy = g_vgs[(g * JJ + j) * 2 + 1];
    float x = (sx + 1.0f) * (WW * 0.5f) - 0.5f;
    float y = (sy + 1.0f) * (HH * 0.5f) - 0.5f;
    float x0f = floorf(x), y0f = floorf(y);
    int x0 = (int)x0f, y0 = (int)y0f;
    float wx1 = x - x0f, wy1 = y - y0f;
    float wx0 = 1.0f - wx1, wy0 = 1.0f - wy1;
    const float* img = &x2[(size_t)(g * (DIM / G) + c) * SEQ + 1];
    float acc = 0.f;
#pragma unroll
    for (int dy = 0; dy < 2; dy++) {
#pragma unroll
        for (int dx = 0; dx < 2; dx++) {
            int ix = x0 + dx, iy = y0 + dy;
            float w = (dx ? wx1 : wx0) * (dy ? wy1 : wy0);
            if (ix >= 0 && ix < WW && iy >= 0 && iy < HH)
                acc += img[iy * WW + ix] * w;
        }
    }
    g_kv[(size_t)(g * (DIM / G) + c) * JJ + j] = acc;
}

// ---------------- CPB bias MLP on tensor cores (tf32 mma.sync) ----------------
__device__ __forceinline__ void mma_tf32(float* d, const uint32_t* a,
                                         uint32_t b0, uint32_t b1) {
    asm volatile(
        "mma.sync.aligned.m16n8k8.row.col.f32.tf32.tf32.f32 "
        "{%0,%1,%2,%3}, {%4,%5,%6,%7}, {%8,%9}, {%0,%1,%2,%3};\n"
        : "+f"(d[0]), "+f"(d[1]), "+f"(d[2]), "+f"(d[3])
        : "r"(a[0]), "r"(a[1]), "r"(a[2]), "r"(a[3]), "r"(b0), "r"(b1));
}

__device__ __forceinline__ uint32_t f2tf32(float f) {
    uint32_t v;
    asm("cvt.rna.tf32.f32 %0, %1;" : "=r"(v) : "f"(f));
    return v;
}

__global__ void cpb_mma_kernel(const float* __restrict__ W1, const float* __restrict__ B1,
                               const float* __restrict__ W2, const float* __restrict__ B2,
                               const float* __restrict__ W3, const float* __restrict__ B3) {
    __shared__ uint32_t H1s[64][68];   // tf32 bits, padded
    __shared__ uint32_t W2s[64][68];   // tf32 bits, W2[k][n]
    __shared__ float W1s[128], B1s[64], B2s[64], W3s[128];

    const int t = threadIdx.x;  // 0..63

    // --- stage weights ---
    for (int idx = t; idx < 64 * 64; idx += 64) {
        int k = idx >> 6, n = idx & 63;
        W2s[k][n] = f2tf32(W2[idx]);
    }
    W1s[t] = W1[t];
    W1s[t + 64] = W1[t + 64];
    B1s[t] = B1[t];
    B2s[t] = B2[t];
    W3s[t] = W3[t];
    W3s[t + 64] = W3[t + 64];
    __syncthreads();

    // --- layer 1: each thread computes h1 for its point ---
    {
        const int p = blockIdx.x * 64 + t;
        const int g = p / PTS_PER_G;
        const int rem = p - g * PTS_PER_G;
        const int i = rem / JJ;
        const int j = rem - i * JJ;
        const float gqx = 2.0f * (float)(i % WW) / (float)(WW - 1) - 1.0f;
        const float gqy = 2.0f * (float)(i / WW) / (float)(HH - 1) - 1.0f;
        const float px = gqx - g_vgs[(g * JJ + j) * 2 + 0];
        const float py = gqy - g_vgs[(g * JJ + j) * 2 + 1];
        const float fx = copysignf(log1pf(fabsf(px)), px);
        const float fy = copysignf(log1pf(fabsf(py)), py);
#pragma unroll
        for (int m = 0; m < 64; m++) {
            float h = fmaxf(fmaf(fx, W1s[m], fmaf(fy, W1s[64 + m], B1s[m])), 0.f);
            H1s[t][m] = f2tf32(h);
        }
    }
    __syncthreads();

    // --- layer 2: 32x64x64 per warp via m16n8k8 tf32 ---
    const int w = t >> 5, lane = t & 31;
    const int gid = lane >> 2, tig = lane & 3;
    const int r0 = w * 32 + gid;

    float acc[2][8][4];
#pragma unroll
    for (int mt = 0; mt < 2; mt++)
#pragma unroll
        for (int nt = 0; nt < 8; nt++)
#pragma unroll
            for (int c = 0; c < 4; c++) acc[mt][nt][c] = 0.f;

#pragma unroll
    for (int k0 = 0; k0 < 64; k0 += 8) {
        uint32_t a[2][4];
#pragma unroll
        for (int mt = 0; mt < 2; mt++) {
            a[mt][0] = H1s[r0 + mt * 16][k0 + tig];
            a[mt][1] = H1s[r0 + mt * 16 + 8][k0 + tig];
            a[mt][2] = H1s[r0 + mt * 16][k0 + tig + 4];
            a[mt][3] = H1s[r0 + mt * 16 + 8][k0 + tig + 4];
        }
#pragma unroll
        for (int nt = 0; nt < 8; nt++) {
            uint32_t b0 = W2s[k0 + tig][nt * 8 + gid];
            uint32_t b1 = W2s[k0 + tig + 4][nt * 8 + gid];
            mma_tf32(acc[0][nt], a[0], b0, b1);
            mma_tf32(acc[1][nt], a[1], b0, b1);
        }
    }

    // --- epilogue: +B2, relu, xW3, reduce over quad, write two heads ---
    const float b30 = B3[0], b31 = B3[1];
#pragma unroll
    for (int mt = 0; mt < 2; mt++) {
        float sa0 = 0.f, sa1 = 0.f;
        float sb0 = 0.f, sb1 = 0.f;
#pragma unroll
        for (int nt = 0; nt < 8; nt++) {
            int n0 = nt * 8 + 2 * tig;
            int n1 = n0 + 1;
            float h;
            h = fmaxf(acc[mt][nt][0] + B2s[n0], 0.f);
            sa0 += h * W3s[2 * n0]; sa1 += h * W3s[2 * n0 + 1];
            h = fmaxf(acc[mt][nt][1] + B2s[n1], 0.f);
            sa0 += h * W3s[2 * n1]; sa1 += h * W3s[2 * n1 + 1];
            h = fmaxf(acc[mt][nt][2] + B2s[n0], 0.f);
            sb0 += h * W3s[2 * n0]; sb1 += h * W3s[2 * n0 + 1];
            h = fmaxf(acc[mt][nt][3] + B2s[n1], 0.f);
            sb0 += h * W3s[2 * n1]; sb1 += h * W3s[2 * n1 + 1];
        }
#pragma unroll
        for (int off = 1; off <= 2; off <<= 1) {
            sa0 += __shfl_xor_sync(0xffffffffu, sa0, off);
            sa1 += __shfl_xor_sync(0xffffffffu, sa1, off);
            sb0 += __shfl_xor_sync(0xffffffffu, sb0, off);
            sb1 += __shfl_xor_sync(0xffffffffu, sb1, off);
        }
        if (tig == 0) {
#pragma unroll
            for (int half = 0; half < 2; half++) {
                int row = w * 32 + mt * 16 + gid + half * 8;
                float o0 = (half ? sb0 : sa0) + b30;
                float o1 = (half ? sb1 : sa1) + b31;
                int pp = blockIdx.x * 64 + row;
                int gg = pp / PTS_PER_G;
                int rr = pp - gg * PTS_PER_G;
                int ii = rr / JJ;
                int jj = rr - ii * JJ;
                size_t base = ((size_t)(gg * 2) * NPOS + ii) * JJ + jj;
                g_bias[base] = o0;
                g_bias[base + (size_t)NPOS * JJ] = o1;
            }
        }
    }
}

// ---------------- fused sim + bias + softmax + out ----------------
__global__ void attn_kernel() {
    const int h = blockIdx.y;
    const int i0 = blockIdx.x * 8;
    __shared__ float qs[8][64];
    __shared__ float ps[8][JJ];
    __shared__ float rsum[8];
    const int tid = threadIdx.x;

    for (int t = tid; t < 8 * 64; t += 256) {
        int r = t >> 6, d = t & 63;
        int i = i0 + r;
        qs[r][d] = (i < NPOS) ? g_q[(size_t)(h * 64 + d) * NPOS + i] * SCALE : 0.f;
    }
    __syncthreads();

    for (int t = tid; t < 8 * JJ; t += 256) {
        int r = t / JJ, j = t % JJ;
        int i = i0 + r;
        float s = 0.f;
#pragma unroll 8
        for (int d = 0; d < 64; d++)
            s += qs[r][d] * g_k[(size_t)(h * 64 + d) * JJ + j];
        if (i < NPOS) s += g_bias[((size_t)h * NPOS + i) * JJ + j];
        ps[r][j] = s;
    }
    __syncthreads();

    const int w = tid >> 5, lane = tid & 31;
    {
        float m = -1e30f;
        for (int j = lane; j < JJ; j += 32) m = fmaxf(m, ps[w][j]);
#pragma unroll
        for (int o = 16; o; o >>= 1) m = fmaxf(m, __shfl_xor_sync(0xffffffffu, m, o));
        float s = 0.f;
        for (int j = lane; j < JJ; j += 32) {
            float e = expf(ps[w][j] - m);
            ps[w][j] = e;
            s += e;
        }
#pragma unroll
        for (int o = 16; o; o >>= 1) s += __shfl_xor_sync(0xffffffffu, s, o);
        if (lane == 0) rsum[w] = s;
    }
    __syncthreads();

    for (int t = tid; t < 8 * 64; t += 256) {
        int r = t >> 6, d = t & 63;
        int i = i0 + r;
        if (i >= NPOS) continue;
        const float* vrow = &g_v[(size_t)(h * 64 + d) * JJ];
        float o = 0.f;
#pragma unroll 8
        for (int j = 0; j < JJ; j++) o += ps[r][j] * vrow[j];
        g_ao[(size_t)(h * 64 + d) * NPOS + i] = o / rsum[r];
    }
}

// ---------------- cls passthrough ----------------
__global__ void cls_kernel(const float* __restrict__ x1, float* __restrict__ out) {
    int o = threadIdx.x;   // 256 threads
    out[(size_t)o * SEQ] = x1[(size_t)o * SEQ];
}

// ---------------- launcher ----------------
extern "C" void kernel_launch(void* const* d_in, const int* in_sizes, int n_in,
                              void* d_out, int out_size) {
    const float* x1    = (const float*)d_in[0];
    const float* x2    = (const float*)d_in[1];
    const float* w_off1= (const float*)d_in[2];
    const float* b_off1= (const float*)d_in[3];
    const float* w_off2= (const float*)d_in[4];
    const float* wq    = (const float*)d_in[5];
    const float* wk    = (const float*)d_in[6];
    const float* wv    = (const float*)d_in[7];
    const float* wout  = (const float*)d_in[8];
    const float* bout  = (const float*)d_in[9];
    const float* cpb_w1= (const float*)d_in[10];
    const float* cpb_b1= (const float*)d_in[11];
    const float* cpb_w2= (const float*)d_in[12];
    const float* cpb_b2= (const float*)d_in[13];
    const float* cpb_w3= (const float*)d_in[14];
    const float* cpb_b3= (const float*)d_in[15];
    float* out = (float*)d_out;

    float *qp, *kvp, *kp, *vp, *aop;
    cudaGetSymbolAddress((void**)&qp,  g_q);
    cudaGetSymbolAddress((void**)&kvp, g_kv);
    cudaGetSymbolAddress((void**)&kp,  g_k);
    cudaGetSymbolAddress((void**)&vp,  g_v);
    cudaGetSymbolAddress((void**)&aop, g_ao);

    // 1) q = wq @ f1   (512 x 2500, K=256)
    sgemm64<<<dim3(40, 8), 256>>>(wq, x1, qp, INNER, NPOS, DIM, SEQ, 1, NPOS, 0, nullptr);

    // 2) depthwise conv + gelu
    dconv_kernel<<<INNER, JJ>>>(w_off1, b_off1);

    // 3) 1x1 conv + tanh + grid
    offgrid_kernel<<<G, JJ>>>(w_off2);

    // 4) bilinear sample
    gsample_kernel<<<G * JJ, 64>>>(x2);

    // 5) k, v GEMMs (512 x 144, K=256)
    sgemm64<<<dim3(3, 8), 256>>>(wk, kvp, kp, INNER, JJ, DIM, JJ, 0, JJ, 0, nullptr);
    sgemm64<<<dim3(3, 8), 256>>>(wv, kvp, vp, INNER, JJ, DIM, JJ, 0, JJ, 0, nullptr);

    // 6) CPB bias MLP on tensor cores
    cpb_mma_kernel<<<PTS_TOTAL / 64, 64>>>(cpb_w1, cpb_b1, cpb_w2, cpb_b2,
                                           cpb_w3, cpb_b3);

    // 7) attention: sim + bias + softmax + out
    attn_kernel<<<dim3((NPOS + 7) / 8, HEADS), 256>>>();

    // 8) wout @ attn_out + bout -> output columns 1..2500
    sgemm64<<<dim3(40, 4), 256>>>(wout, aop, out, DIM, NPOS, INNER, NPOS, 0, SEQ, 1, bout);

    // 9) cls token passthrough -> column 0
    cls_kernel<<<1, DIM>>>(x1, out);
}

// round 5
// speedup vs baseline: 2.6704x; 1.9086x over previous
#include <cuda_runtime.h>
#include <cuda_bf16.h>
#include <math.h>
#include <stdint.h>

// ---------------- problem constants ----------------
#define HH 50
#define WW 50
#define NPOS 2500          // H*W
#define DIM 256
#define HEADS 8
#define DH 64
#define G 4
#define INNER 512          // HEADS*DH
#define OFFD 128           // INNER/G
#define CPB 64             // DIM/4
#define O 2                // HEADS/G
#define KS 6
#define DF 4
#define PAD 1
#define HK 12
#define JJ 144             // HK*HK
#define SCALE 0.125f
#define OFF_SCALE 4.0f
#define SEQ 2501           // H*W+1
#define PTS_TOTAL (G * NPOS * JJ)   // 1,440,000
#define PTS_PER_G (NPOS * JJ)       // 360,000

// cpb-v3 tiling: 750 blocks x 15 iters x 128 points = 1,440,000
#define CPB_BLOCKS 750
#define CPB_ITERS 15
#define H1PAD 40
#define W2PAD 72

// ---------------- scratch (device globals, no allocation) ----------------
__device__ float g_q[INNER * NPOS];          // q = wq @ f1         (512 x 2500)
__device__ float g_off1[INNER * JJ];         // gelu(depthwise conv) (4*128 x 144)
__device__ float g_vgs[G * JJ * 2];          // normalized sample grid
__device__ float g_kv[DIM * JJ];             // sampled features     (256 x 144)
__device__ float g_k[INNER * JJ];            // k                   (512 x 144)
__device__ float g_v[INNER * JJ];            // v                   (512 x 144)
__device__ float g_bias[HEADS * NPOS * JJ];  // CPB bias per head   (8 x 2500 x 144)
__device__ float g_ao[INNER * NPOS];         // attention output    (512 x 2500)

// ---------------- generic tiled SGEMM ----------------
__global__ void sgemm64(const float* __restrict__ A, const float* __restrict__ B,
                        float* __restrict__ C, int M, int N, int K,
                        int ldb, int boff, int ldc, int coff,
                        const float* __restrict__ bias) {
    __shared__ float As[16][64 + 1];
    __shared__ float Bs[16][64 + 1];
    const int tx = threadIdx.x & 15;   // n dir
    const int ty = threadIdx.x >> 4;   // m dir
    const int m0 = blockIdx.y * 64;
    const int n0 = blockIdx.x * 64;
    float acc[4][4];
#pragma unroll
    for (int u = 0; u < 4; u++)
#pragma unroll
        for (int w = 0; w < 4; w++) acc[u][w] = 0.f;

    for (int k0 = 0; k0 < K; k0 += 16) {
        for (int t = threadIdx.x; t < 64 * 16; t += 256) {
            int m = t >> 4, k = t & 15;
            float v = 0.f;
            if (m0 + m < M) v = A[(size_t)(m0 + m) * K + k0 + k];
            As[k][m] = v;
        }
        for (int t = threadIdx.x; t < 64 * 16; t += 256) {
            int k = t >> 6, n = t & 63;
            float v = 0.f;
            if (n0 + n < N) v = B[(size_t)(k0 + k) * ldb + boff + n0 + n];
            Bs[k][n] = v;
        }
        __syncthreads();
#pragma unroll
        for (int k = 0; k < 16; k++) {
            float a[4], b[4];
#pragma unroll
            for (int u = 0; u < 4; u++) a[u] = As[k][ty * 4 + u];
#pragma unroll
            for (int w = 0; w < 4; w++) b[w] = Bs[k][tx * 4 + w];
#pragma unroll
            for (int u = 0; u < 4; u++)
#pragma unroll
                for (int w = 0; w < 4; w++) acc[u][w] += a[u] * b[w];
        }
        __syncthreads();
    }
#pragma unroll
    for (int u = 0; u < 4; u++) {
        int m = m0 + ty * 4 + u;
        if (m >= M) continue;
        float bb = bias ? bias[m] : 0.f;
#pragma unroll
        for (int w = 0; w < 4; w++) {
            int n = n0 + tx * 4 + w;
            if (n < N) C[(size_t)m * ldc + coff + n] = acc[u][w] + bb;
        }
    }
}

// ---------------- depthwise conv (stride 4, pad 1, 6x6) + bias + exact GELU ----------------
__global__ void dconv_kernel(const float* __restrict__ w1, const float* __restrict__ b1) {
    const int gc = blockIdx.x;          // 0..511
    const int c = gc & 127;
    const int j = threadIdx.x;          // 0..143
    const int oy = j / HK, ox = j % HK;
    const float* qrow = &g_q[(size_t)gc * NPOS];
    const float* wt = &w1[c * 36];
    float acc = 0.f;
#pragma unroll
    for (int ky = 0; ky < KS; ky++) {
        int iy = oy * DF - PAD + ky;
        if (iy < 0 || iy >= HH) continue;
#pragma unroll
        for (int kx = 0; kx < KS; kx++) {
            int ix = ox * DF - PAD + kx;
            if (ix < 0 || ix >= WW) continue;
            acc += qrow[iy * WW + ix] * wt[ky * KS + kx];
        }
    }
    float x = acc + b1[c];
    float gl = 0.5f * x * (1.0f + erff(x * 0.70710678118654752f));
    g_off1[(size_t)gc * JJ + j] = gl;
}

// ---------------- 1x1 conv + tanh*4 + build normalized sampling grid ----------------
__global__ void offgrid_kernel(const float* __restrict__ w2) {
    const int g = blockIdx.x;   // 0..3
    const int j = threadIdx.x;  // 0..143
    float s0 = 0.f, s1 = 0.f;
    for (int c = 0; c < OFFD; c++) {
        float v = g_off1[(size_t)(g * OFFD + c) * JJ + j];
        s0 += w2[c] * v;
        s1 += w2[OFFD + c] * v;
    }
    float offx = tanhf(s0) * OFF_SCALE;
    float offy = tanhf(s1) * OFF_SCALE;
    int x = j % HK, y = j / HK;
    float vx = (float)x + offx;
    float vy = (float)y + offy;
    float sx = 2.0f * vx / (float)(HK - 1) - 1.0f;
    float sy = 2.0f * vy / (float)(HK - 1) - 1.0f;
    g_vgs[(g * JJ + j) * 2 + 0] = sx;
    g_vgs[(g * JJ + j) * 2 + 1] = sy;
}

// ---------------- bilinear grid sample of f2 ----------------
__global__ void gsample_kernel(const float* __restrict__ x2) {
    const int blk = blockIdx.x;
    const int g = blk / JJ;
    const int j = blk % JJ;
    const int c = threadIdx.x;     // 0..63
    float sx = g_vgs[(g * JJ + j) * 2 + 0];
    float sy = g_vgs[(g * JJ + j) * 2 + 1];
    float x = (sx + 1.0f) * (WW * 0.5f) - 0.5f;
    float y = (sy + 1.0f) * (HH * 0.5f) - 0.5f;
    float x0f = floorf(x), y0f = floorf(y);
    int x0 = (int)x0f, y0 = (int)y0f;
    float wx1 = x - x0f, wy1 = y - y0f;
    float wx0 = 1.0f - wx1, wy0 = 1.0f - wy1;
    const float* img = &x2[(size_t)(g * (DIM / G) + c) * SEQ + 1];
    float acc = 0.f;
#pragma unroll
    for (int dy = 0; dy < 2; dy++) {
#pragma unroll
        for (int dx = 0; dx < 2; dx++) {
            int ix = x0 + dx, iy = y0 + dy;
            float w = (dx ? wx1 : wx0) * (dy ? wy1 : wy0);
            if (ix >= 0 && ix < WW && iy >= 0 && iy < HH)
                acc += img[iy * WW + ix] * w;
        }
    }
    g_kv[(size_t)(g * (DIM / G) + c) * JJ + j] = acc;
}

// ---------------- CPB bias MLP: bf16 m16n8k16 mma, multi-tile per block ----------------
__device__ __forceinline__ void mma_bf16(float* d, const uint32_t* a,
                                         uint32_t b0, uint32_t b1) {
    asm volatile(
        "mma.sync.aligned.m16n8k16.row.col.f32.bf16.bf16.f32 "
        "{%0,%1,%2,%3}, {%4,%5,%6,%7}, {%8,%9}, {%0,%1,%2,%3};\n"
        : "+f"(d[0]), "+f"(d[1]), "+f"(d[2]), "+f"(d[3])
        : "r"(a[0]), "r"(a[1]), "r"(a[2]), "r"(a[3]), "r"(b0), "r"(b1));
}

__device__ __forceinline__ uint32_t pack_bf16x2(float lo, float hi) {
    __nv_bfloat162 p = __floats2bfloat162_rn(lo, hi);  // x = lo, y = hi
    return *reinterpret_cast<uint32_t*>(&p);
}

__global__ __launch_bounds__(128)
void cpb_mma_kernel(const float* __restrict__ W1, const float* __restrict__ B1,
                    const float* __restrict__ W2, const float* __restrict__ B2,
                    const float* __restrict__ W3, const float* __restrict__ B3) {
    __shared__ uint32_t H1s[128][H1PAD];   // bf16x2: [row][k-pair], 20.5KB
    __shared__ uint32_t W2s[32][W2PAD];    // bf16x2: [k-pair][n],   9.2KB
    __shared__ float W1s[128], B1s[64], B2s[64], W3s[128];

    const int t = threadIdx.x;  // 0..127

    // --- stage weights (once per block) ---
    for (int idx = t; idx < 32 * 64; idx += 128) {
        int kk = idx >> 6, n = idx & 63;
        W2s[kk][n] = pack_bf16x2(W2[(2 * kk) * 64 + n], W2[(2 * kk + 1) * 64 + n]);
    }
    if (t < 128) W1s[t] = W1[t];
    if (t < 64) { B1s[t] = B1[t]; B2s[t] = B2[t]; }
    if (t < 128) W3s[t] = W3[t];
    __syncthreads();

    const int w = t >> 5, lane = t & 31;
    const int gid = lane >> 2, tig = lane & 3;
    const int r0 = w * 32 + gid;
    const float b30 = B3[0], b31 = B3[1];

    for (int it = 0; it < CPB_ITERS; it++) {
        const int base = (blockIdx.x * CPB_ITERS + it) * 128;

        // --- layer 1: each thread computes h1 for its point, packs bf16x2 ---
        {
            const int p = base + t;
            const int g = p / PTS_PER_G;
            const int rem = p - g * PTS_PER_G;
            const int i = rem / JJ;
            const int j = rem - i * JJ;
            const float gqx = 2.0f * (float)(i % WW) / (float)(WW - 1) - 1.0f;
            const float gqy = 2.0f * (float)(i / WW) / (float)(HH - 1) - 1.0f;
            const float px = gqx - g_vgs[(g * JJ + j) * 2 + 0];
            const float py = gqy - g_vgs[(g * JJ + j) * 2 + 1];
            const float fx = copysignf(log1pf(fabsf(px)), px);
            const float fy = copysignf(log1pf(fabsf(py)), py);
            float h[64];
#pragma unroll
            for (int m = 0; m < 64; m++)
                h[m] = fmaxf(fmaf(fx, W1s[m], fmaf(fy, W1s[64 + m], B1s[m])), 0.f);
#pragma unroll
            for (int kk = 0; kk < 32; kk++)
                H1s[t][kk] = pack_bf16x2(h[2 * kk], h[2 * kk + 1]);
        }
        __syncthreads();

        // --- layer 2: each warp 32x64x64 via m16n8k16 bf16 ---
        float acc[2][8][4];
#pragma unroll
        for (int mt = 0; mt < 2; mt++)
#pragma unroll
            for (int nt = 0; nt < 8; nt++)
#pragma unroll
                for (int c = 0; c < 4; c++) acc[mt][nt][c] = 0.f;

#pragma unroll
        for (int kk0 = 0; kk0 < 32; kk0 += 8) {
            uint32_t a[2][4];
#pragma unroll
            for (int mt = 0; mt < 2; mt++) {
                a[mt][0] = H1s[r0 + mt * 16][kk0 + tig];
                a[mt][1] = H1s[r0 + mt * 16 + 8][kk0 + tig];
                a[mt][2] = H1s[r0 + mt * 16][kk0 + tig + 4];
                a[mt][3] = H1s[r0 + mt * 16 + 8][kk0 + tig + 4];
            }
#pragma unroll
            for (int nt = 0; nt < 8; nt++) {
                uint32_t b0 = W2s[kk0 + tig][nt * 8 + gid];
                uint32_t b1 = W2s[kk0 + tig + 4][nt * 8 + gid];
                mma_bf16(acc[0][nt], a[0], b0, b1);
                mma_bf16(acc[1][nt], a[1], b0, b1);
            }
        }

        // --- epilogue: +B2, relu, xW3, quad-reduce, write two heads ---
#pragma unroll
        for (int mt = 0; mt < 2; mt++) {
            float sa0 = 0.f, sa1 = 0.f;  // row r0 + mt*16
            float sb0 = 0.f, sb1 = 0.f;  // row r0 + mt*16 + 8
#pragma unroll
            for (int nt = 0; nt < 8; nt++) {
                int n0 = nt * 8 + 2 * tig;
                int n1 = n0 + 1;
                float h;
                h = fmaxf(acc[mt][nt][0] + B2s[n0], 0.f);
                sa0 += h * W3s[2 * n0]; sa1 += h * W3s[2 * n0 + 1];
                h = fmaxf(acc[mt][nt][1] + B2s[n1], 0.f);
                sa0 += h * W3s[2 * n1]; sa1 += h * W3s[2 * n1 + 1];
                h = fmaxf(acc[mt][nt][2] + B2s[n0], 0.f);
                sb0 += h * W3s[2 * n0]; sb1 += h * W3s[2 * n0 + 1];
                h = fmaxf(acc[mt][nt][3] + B2s[n1], 0.f);
                sb0 += h * W3s[2 * n1]; sb1 += h * W3s[2 * n1 + 1];
            }
#pragma unroll
            for (int off = 1; off <= 2; off <<= 1) {
                sa0 += __shfl_xor_sync(0xffffffffu, sa0, off);
                sa1 += __shfl_xor_sync(0xffffffffu, sa1, off);
                sb0 += __shfl_xor_sync(0xffffffffu, sb0, off);
                sb1 += __shfl_xor_sync(0xffffffffu, sb1, off);
            }
            if (tig == 0) {
#pragma unroll
                for (int half = 0; half < 2; half++) {
                    int row = w * 32 + mt * 16 + gid + half * 8;
                    float o0 = (half ? sb0 : sa0) + b30;
                    float o1 = (half ? sb1 : sa1) + b31;
                    int pp = base + row;
                    int gg = pp / PTS_PER_G;
                    int rr = pp - gg * PTS_PER_G;
                    int ii = rr / JJ;
                    int jj = rr - ii * JJ;
                    size_t bofs = ((size_t)(gg * 2) * NPOS + ii) * JJ + jj;
                    g_bias[bofs] = o0;
                    g_bias[bofs + (size_t)NPOS * JJ] = o1;
                }
            }
        }
        __syncthreads();   // protect H1s before next iteration overwrites
    }
}

// ---------------- fused sim + bias + softmax + out (32 rows/block) ----------------
__global__ void attn_kernel() {
    const int h = blockIdx.y;
    const int i0 = blockIdx.x * 32;
    __shared__ float qs[32][65];
    __shared__ float ps[32][145];
    __shared__ float rsum[32];
    const int tid = threadIdx.x;  // 0..255

    // load q tile (coalesced over i)
    for (int idx = tid; idx < 32 * 64; idx += 256) {
        int r = idx & 31, d = idx >> 5;
        int i = i0 + r;
        qs[r][d] = (i < NPOS) ? g_q[(size_t)(h * 64 + d) * NPOS + i] * SCALE : 0.f;
    }
    __syncthreads();

    // sim + bias
    for (int idx = tid; idx < 32 * JJ; idx += 256) {
        int r = idx / JJ, j = idx - r * JJ;
        int i = i0 + r;
        float s = 0.f;
#pragma unroll 8
        for (int d = 0; d < 64; d++)
            s += qs[r][d] * g_k[(size_t)(h * 64 + d) * JJ + j];
        if (i < NPOS) s += g_bias[((size_t)h * NPOS + i) * JJ + j];
        else s = 0.f;
        ps[r][j] = s;
    }
    __syncthreads();

    // softmax: warp w owns rows {w, w+8, w+16, w+24}
    const int w = tid >> 5, lane = tid & 31;
#pragma unroll
    for (int rr = 0; rr < 4; rr++) {
        int row = w + rr * 8;
        float m = -1e30f;
        for (int j = lane; j < JJ; j += 32) m = fmaxf(m, ps[row][j]);
#pragma unroll
        for (int o = 16; o; o >>= 1) m = fmaxf(m, __shfl_xor_sync(0xffffffffu, m, o));
        float s = 0.f;
        for (int j = lane; j < JJ; j += 32) {
            float e = expf(ps[row][j] - m);
            ps[row][j] = e;
            s += e;
        }
#pragma unroll
        for (int o = 16; o; o >>= 1) s += __shfl_xor_sync(0xffffffffu, s, o);
        if (lane == 0) rsum[row] = s;
    }
    __syncthreads();

    // out: lanes span r (coalesced stores over i), d broadcast per warp-step
    for (int idx = tid; idx < 32 * 64; idx += 256) {
        int r = idx & 31, d = idx >> 5;
        int i = i0 + r;
        if (i >= NPOS) continue;
        const float* vrow = &g_v[(size_t)(h * 64 + d) * JJ];
        float o = 0.f;
#pragma unroll 8
        for (int j = 0; j < JJ; j++) o += ps[r][j] * vrow[j];
        g_ao[(size_t)(h * 64 + d) * NPOS + i] = o / rsum[r];
    }
}

// ---------------- cls passthrough ----------------
__global__ void cls_kernel(const float* __restrict__ x1, float* __restrict__ out) {
    int o = threadIdx.x;   // 256 threads
    out[(size_t)o * SEQ] = x1[(size_t)o * SEQ];
}

// ---------------- launcher ----------------
extern "C" void kernel_launch(void* const* d_in, const int* in_sizes, int n_in,
                              void* d_out, int out_size) {
    const float* x1    = (const float*)d_in[0];
    const float* x2    = (const float*)d_in[1];
    const float* w_off1= (const float*)d_in[2];
    const float* b_off1= (const float*)d_in[3];
    const float* w_off2= (const float*)d_in[4];
    const float* wq    = (const float*)d_in[5];
    const float* wk    = (const float*)d_in[6];
    const float* wv    = (const float*)d_in[7];
    const float* wout  = (const float*)d_in[8];
    const float* bout  = (const float*)d_in[9];
    const float* cpb_w1= (const float*)d_in[10];
    const float* cpb_b1= (const float*)d_in[11];
    const float* cpb_w2= (const float*)d_in[12];
    const float* cpb_b2= (const float*)d_in[13];
    const float* cpb_w3= (const float*)d_in[14];
    const float* cpb_b3= (const float*)d_in[15];
    float* out = (float*)d_out;

    float *qp, *kvp, *kp, *vp, *aop;
    cudaGetSymbolAddress((void**)&qp,  g_q);
    cudaGetSymbolAddress((void**)&kvp, g_kv);
    cudaGetSymbolAddress((void**)&kp,  g_k);
    cudaGetSymbolAddress((void**)&vp,  g_v);
    cudaGetSymbolAddress((void**)&aop, g_ao);

    // 1) q = wq @ f1   (512 x 2500, K=256)
    sgemm64<<<dim3(40, 8), 256>>>(wq, x1, qp, INNER, NPOS, DIM, SEQ, 1, NPOS, 0, nullptr);

    // 2) depthwise conv + gelu
    dconv_kernel<<<INNER, JJ>>>(w_off1, b_off1);

    // 3) 1x1 conv + tanh + grid
    offgrid_kernel<<<G, JJ>>>(w_off2);

    // 4) bilinear sample
    gsample_kernel<<<G * JJ, 64>>>(x2);

    // 5) k, v GEMMs (512 x 144, K=256)
    sgemm64<<<dim3(3, 8), 256>>>(wk, kvp, kp, INNER, JJ, DIM, JJ, 0, JJ, 0, nullptr);
    sgemm64<<<dim3(3, 8), 256>>>(wv, kvp, vp, INNER, JJ, DIM, JJ, 0, JJ, 0, nullptr);

    // 6) CPB bias MLP on tensor cores (bf16, multi-tile)
    cpb_mma_kernel<<<CPB_BLOCKS, 128>>>(cpb_w1, cpb_b1, cpb_w2, cpb_b2,
                                        cpb_w3, cpb_b3);

    // 7) attention: sim + bias + softmax + out
    attn_kernel<<<dim3((NPOS + 31) / 32, HEADS), 256>>>();

    // 8) wout @ attn_out + bout -> output columns 1..2500
    sgemm64<<<dim3(40, 4), 256>>>(wout, aop, out, DIM, NPOS, INNER, NPOS, 0, SEQ, 1, bout);

    // 9) cls token passthrough -> column 0
    cls_kernel<<<1, DIM>>>(x1, out);
}

// round 6
// speedup vs baseline: 3.5854x; 1.3426x over previous
#include <cuda_runtime.h>
#include <cuda_bf16.h>
#include <math.h>
#include <stdint.h>

// ---------------- problem constants ----------------
#define HH 50
#define WW 50
#define NPOS 2500          // H*W
#define DIM 256
#define HEADS 8
#define DH 64
#define G 4
#define INNER 512          // HEADS*DH
#define OFFD 128           // INNER/G
#define CPB 64             // DIM/4
#define O 2                // HEADS/G
#define KS 6
#define DF 4
#define PAD 1
#define HK 12
#define JJ 144             // HK*HK
#define SCALE 0.125f
#define OFF_SCALE 4.0f
#define SEQ 2501           // H*W+1
#define PTS_TOTAL (G * NPOS * JJ)   // 1,440,000
#define PTS_PER_G (NPOS * JJ)       // 360,000

// cpb tiling: 750 blocks x 15 iters x 128 points = 1,440,000
#define CPB_BLOCKS 750
#define CPB_ITERS 15
#define H1PAD 40
#define W2PAD 72

// ---------------- scratch (device globals, no allocation) ----------------
__device__ float g_q[INNER * NPOS];          // q = wq @ f1         (512 x 2500)
__device__ float g_off1[INNER * JJ];         // gelu(depthwise conv) (4*128 x 144)
__device__ float g_vgs[G * JJ * 2];          // normalized sample grid
__device__ float g_kv[DIM * JJ];             // sampled features     (256 x 144)
__device__ float g_k[INNER * JJ];            // k                   (512 x 144)
__device__ float g_v[INNER * JJ];            // v                   (512 x 144)
__device__ float g_bias[HEADS * NPOS * JJ];  // CPB bias per head   (8 x 2500 x 144)
__device__ float g_ao[INNER * NPOS];         // attention output    (512 x 2500)

// ---------------- mma helpers ----------------
__device__ __forceinline__ void mma_tf32(float* d, const uint32_t* a,
                                         uint32_t b0, uint32_t b1) {
    asm volatile(
        "mma.sync.aligned.m16n8k8.row.col.f32.tf32.tf32.f32 "
        "{%0,%1,%2,%3}, {%4,%5,%6,%7}, {%8,%9}, {%0,%1,%2,%3};\n"
        : "+f"(d[0]), "+f"(d[1]), "+f"(d[2]), "+f"(d[3])
        : "r"(a[0]), "r"(a[1]), "r"(a[2]), "r"(a[3]), "r"(b0), "r"(b1));
}

__device__ __forceinline__ void mma_bf16(float* d, const uint32_t* a,
                                         uint32_t b0, uint32_t b1) {
    asm volatile(
        "mma.sync.aligned.m16n8k16.row.col.f32.bf16.bf16.f32 "
        "{%0,%1,%2,%3}, {%4,%5,%6,%7}, {%8,%9}, {%0,%1,%2,%3};\n"
        : "+f"(d[0]), "+f"(d[1]), "+f"(d[2]), "+f"(d[3])
        : "r"(a[0]), "r"(a[1]), "r"(a[2]), "r"(a[3]), "r"(b0), "r"(b1));
}

__device__ __forceinline__ uint32_t f2tf32(float f) {
    uint32_t v;
    asm("cvt.rna.tf32.f32 %0, %1;" : "=r"(v) : "f"(f));
    return v;
}

__device__ __forceinline__ uint32_t pack_bf16x2(float lo, float hi) {
    __nv_bfloat162 p = __floats2bfloat162_rn(lo, hi);
    return *reinterpret_cast<uint32_t*>(&p);
}

// ---------------- 3xTF32 split-precision tensor-core GEMM ----------------
// C[m, ldc*m + coff + n] = sum_k A[m*K+k] * B[k*ldb + boff + n] (+ bias[m])
// Requires: M % 64 == 0, K % 32 == 0. N arbitrary (bounds-checked).
__global__ __launch_bounds__(256)
void tf32gemm(const float* __restrict__ A, const float* __restrict__ B,
              float* __restrict__ C, int M, int N, int K,
              int ldb, int boff, int ldc, int coff,
              const float* __restrict__ bias) {
    __shared__ uint32_t Ah[64][36], Al[64][36];   // [m][k], bank-clean
    __shared__ uint32_t Bh[32][72], Bl[32][72];   // [k][n], bank-clean
    const int tid = threadIdx.x;
    const int m0 = blockIdx.y * 64, n0 = blockIdx.x * 64;
    const int wid = tid >> 5, lane = tid & 31;
    const int gid = lane >> 2, tig = lane & 3;
    const int wm = (wid >> 1) * 16, wn = (wid & 1) * 32;

    float acc[4][4];
#pragma unroll
    for (int nt = 0; nt < 4; nt++)
#pragma unroll
        for (int c = 0; c < 4; c++) acc[nt][c] = 0.f;

    for (int k0 = 0; k0 < K; k0 += 32) {
        for (int idx = tid; idx < 2048; idx += 256) {
            int m = idx >> 5, k = idx & 31;
            float v = A[(size_t)(m0 + m) * K + k0 + k];
            uint32_t hi = f2tf32(v);
            Ah[m][k] = hi;
            Al[m][k] = f2tf32(v - __uint_as_float(hi));
        }
        for (int idx = tid; idx < 2048; idx += 256) {
            int k = idx >> 6, n = idx & 63;
            float v = (n0 + n < N) ? B[(size_t)(k0 + k) * ldb + boff + n0 + n] : 0.f;
            uint32_t hi = f2tf32(v);
            Bh[k][n] = hi;
            Bl[k][n] = f2tf32(v - __uint_as_float(hi));
        }
        __syncthreads();
#pragma unroll
        for (int ks = 0; ks < 32; ks += 8) {
            uint32_t ah[4], al[4];
            ah[0] = Ah[wm + gid][ks + tig];
            ah[1] = Ah[wm + gid + 8][ks + tig];
            ah[2] = Ah[wm + gid][ks + tig + 4];
            ah[3] = Ah[wm + gid + 8][ks + tig + 4];
            al[0] = Al[wm + gid][ks + tig];
            al[1] = Al[wm + gid + 8][ks + tig];
            al[2] = Al[wm + gid][ks + tig + 4];
            al[3] = Al[wm + gid + 8][ks + tig + 4];
#pragma unroll
            for (int nt = 0; nt < 4; nt++) {
                int nn = wn + nt * 8 + gid;
                uint32_t bh0 = Bh[ks + tig][nn], bh1 = Bh[ks + tig + 4][nn];
                uint32_t bl0 = Bl[ks + tig][nn], bl1 = Bl[ks + tig + 4][nn];
                mma_tf32(acc[nt], ah, bh0, bh1);
                mma_tf32(acc[nt], ah, bl0, bl1);
                mma_tf32(acc[nt], al, bh0, bh1);
            }
        }
        __syncthreads();
    }

    // epilogue
    const int row0 = m0 + wm + gid;
    const float bb0 = bias ? bias[row0] : 0.f;
    const float bb1 = bias ? bias[row0 + 8] : 0.f;
#pragma unroll
    for (int nt = 0; nt < 4; nt++) {
        int col = n0 + wn + nt * 8 + 2 * tig;
        if (col < N) {
            C[(size_t)row0 * ldc + coff + col] = acc[nt][0] + bb0;
            C[(size_t)(row0 + 8) * ldc + coff + col] = acc[nt][2] + bb1;
        }
        if (col + 1 < N) {
            C[(size_t)row0 * ldc + coff + col + 1] = acc[nt][1] + bb0;
            C[(size_t)(row0 + 8) * ldc + coff + col + 1] = acc[nt][3] + bb1;
        }
    }
}

// ---------------- depthwise conv (stride 4, pad 1, 6x6) + bias + exact GELU ----------------
__global__ void dconv_kernel(const float* __restrict__ w1, const float* __restrict__ b1) {
    const int gc = blockIdx.x;          // 0..511
    const int c = gc & 127;
    const int j = threadIdx.x;          // 0..143
    const int oy = j / HK, ox = j % HK;
    const float* qrow = &g_q[(size_t)gc * NPOS];
    const float* wt = &w1[c * 36];
    float acc = 0.f;
#pragma unroll
    for (int ky = 0; ky < KS; ky++) {
        int iy = oy * DF - PAD + ky;
        if (iy < 0 || iy >= HH) continue;
#pragma unroll
        for (int kx = 0; kx < KS; kx++) {
            int ix = ox * DF - PAD + kx;
            if (ix < 0 || ix >= WW) continue;
            acc += qrow[iy * WW + ix] * wt[ky * KS + kx];
        }
    }
    float x = acc + b1[c];
    float gl = 0.5f * x * (1.0f + erff(x * 0.70710678118654752f));
    g_off1[(size_t)gc * JJ + j] = gl;
}

// ---------------- 1x1 conv + tanh*4 + build normalized sampling grid ----------------
__global__ void offgrid_kernel(const float* __restrict__ w2) {
    const int g = blockIdx.x;   // 0..3
    const int j = threadIdx.x;  // 0..143
    float s0 = 0.f, s1 = 0.f;
    for (int c = 0; c < OFFD; c++) {
        float v = g_off1[(size_t)(g * OFFD + c) * JJ + j];
        s0 += w2[c] * v;
        s1 += w2[OFFD + c] * v;
    }
    float offx = tanhf(s0) * OFF_SCALE;
    float offy = tanhf(s1) * OFF_SCALE;
    int x = j % HK, y = j / HK;
    float vx = (float)x + offx;
    float vy = (float)y + offy;
    float sx = 2.0f * vx / (float)(HK - 1) - 1.0f;
    float sy = 2.0f * vy / (float)(HK - 1) - 1.0f;
    g_vgs[(g * JJ + j) * 2 + 0] = sx;
    g_vgs[(g * JJ + j) * 2 + 1] = sy;
}

// ---------------- bilinear grid sample of f2 ----------------
__global__ void gsample_kernel(const float* __restrict__ x2) {
    const int blk = blockIdx.x;
    const int g = blk / JJ;
    const int j = blk % JJ;
    const int c = threadIdx.x;     // 0..63
    float sx = g_vgs[(g * JJ + j) * 2 + 0];
    float sy = g_vgs[(g * JJ + j) * 2 + 1];
    float x = (sx + 1.0f) * (WW * 0.5f) - 0.5f;
    float y = (sy + 1.0f) * (HH * 0.5f) - 0.5f;
    float x0f = floorf(x), y0f = floorf(y);
    int x0 = (int)x0f, y0 = (int)y0f;
    float wx1 = x - x0f, wy1 = y - y0f;
    float wx0 = 1.0f - wx1, wy0 = 1.0f - wy1;
    const float* img = &x2[(size_t)(g * (DIM / G) + c) * SEQ + 1];
    float acc = 0.f;
#pragma unroll
    for (int dy = 0; dy < 2; dy++) {
#pragma unroll
        for (int dx = 0; dx < 2; dx++) {
            int ix = x0 + dx, iy = y0 + dy;
            float w = (dx ? wx1 : wx0) * (dy ? wy1 : wy0);
            if (ix >= 0 && ix < WW && iy >= 0 && iy < HH)
                acc += img[iy * WW + ix] * w;
        }
    }
    g_kv[(size_t)(g * (DIM / G) + c) * JJ + j] = acc;
}

// ---------------- CPB bias MLP: bf16 m16n8k16 mma, multi-tile per block ----------------
__global__ __launch_bounds__(128)
void cpb_mma_kernel(const float* __restrict__ W1, const float* __restrict__ B1,
                    const float* __restrict__ W2, const float* __restrict__ B2,
                    const float* __restrict__ W3, const float* __restrict__ B3) {
    __shared__ uint32_t H1s[128][H1PAD];   // bf16x2: [row][k-pair]
    __shared__ uint32_t W2s[32][W2PAD];    // bf16x2: [k-pair][n]
    __shared__ float W1s[128], B1s[64], B2s[64], W3s[128];

    const int t = threadIdx.x;  // 0..127

    for (int idx = t; idx < 32 * 64; idx += 128) {
        int kk = idx >> 6, n = idx & 63;
        W2s[kk][n] = pack_bf16x2(W2[(2 * kk) * 64 + n], W2[(2 * kk + 1) * 64 + n]);
    }
    if (t < 128) W1s[t] = W1[t];
    if (t < 64) { B1s[t] = B1[t]; B2s[t] = B2[t]; }
    if (t < 128) W3s[t] = W3[t];
    __syncthreads();

    const int w = t >> 5, lane = t & 31;
    const int gid = lane >> 2, tig = lane & 3;
    const int r0 = w * 32 + gid;
    const float b30 = B3[0], b31 = B3[1];

    for (int it = 0; it < CPB_ITERS; it++) {
        const int base = (blockIdx.x * CPB_ITERS + it) * 128;

        {
            const int p = base + t;
            const int g = p / PTS_PER_G;
            const int rem = p - g * PTS_PER_G;
            const int i = rem / JJ;
            const int j = rem - i * JJ;
            const float gqx = 2.0f * (float)(i % WW) / (float)(WW - 1) - 1.0f;
            const float gqy = 2.0f * (float)(i / WW) / (float)(HH - 1) - 1.0f;
            const float px = gqx - g_vgs[(g * JJ + j) * 2 + 0];
            const float py = gqy - g_vgs[(g * JJ + j) * 2 + 1];
            const float fx = copysignf(log1pf(fabsf(px)), px);
            const float fy = copysignf(log1pf(fabsf(py)), py);
            float h[64];
#pragma unroll
            for (int m = 0; m < 64; m++)
                h[m] = fmaxf(fmaf(fx, W1s[m], fmaf(fy, W1s[64 + m], B1s[m])), 0.f);
#pragma unroll
            for (int kk = 0; kk < 32; kk++)
                H1s[t][kk] = pack_bf16x2(h[2 * kk], h[2 * kk + 1]);
        }
        __syncthreads();

        float acc[2][8][4];
#pragma unroll
        for (int mt = 0; mt < 2; mt++)
#pragma unroll
            for (int nt = 0; nt < 8; nt++)
#pragma unroll
                for (int c = 0; c < 4; c++) acc[mt][nt][c] = 0.f;

#pragma unroll
        for (int kk0 = 0; kk0 < 32; kk0 += 8) {
            uint32_t a[2][4];
#pragma unroll
            for (int mt = 0; mt < 2; mt++) {
                a[mt][0] = H1s[r0 + mt * 16][kk0 + tig];
                a[mt][1] = H1s[r0 + mt * 16 + 8][kk0 + tig];
                a[mt][2] = H1s[r0 + mt * 16][kk0 + tig + 4];
                a[mt][3] = H1s[r0 + mt * 16 + 8][kk0 + tig + 4];
            }
#pragma unroll
            for (int nt = 0; nt < 8; nt++) {
                uint32_t b0 = W2s[kk0 + tig][nt * 8 + gid];
                uint32_t b1 = W2s[kk0 + tig + 4][nt * 8 + gid];
                mma_bf16(acc[0][nt], a[0], b0, b1);
                mma_bf16(acc[1][nt], a[1], b0, b1);
            }
        }

#pragma unroll
        for (int mt = 0; mt < 2; mt++) {
            float sa0 = 0.f, sa1 = 0.f;
            float sb0 = 0.f, sb1 = 0.f;
#pragma unroll
            for (int nt = 0; nt < 8; nt++) {
                int n0 = nt * 8 + 2 * tig;
                int n1 = n0 + 1;
                float h;
                h = fmaxf(acc[mt][nt][0] + B2s[n0], 0.f);
                sa0 += h * W3s[2 * n0]; sa1 += h * W3s[2 * n0 + 1];
                h = fmaxf(acc[mt][nt][1] + B2s[n1], 0.f);
                sa0 += h * W3s[2 * n1]; sa1 += h * W3s[2 * n1 + 1];
                h = fmaxf(acc[mt][nt][2] + B2s[n0], 0.f);
                sb0 += h * W3s[2 * n0]; sb1 += h * W3s[2 * n0 + 1];
                h = fmaxf(acc[mt][nt][3] + B2s[n1], 0.f);
                sb0 += h * W3s[2 * n1]; sb1 += h * W3s[2 * n1 + 1];
            }
#pragma unroll
            for (int off = 1; off <= 2; off <<= 1) {
                sa0 += __shfl_xor_sync(0xffffffffu, sa0, off);
                sa1 += __shfl_xor_sync(0xffffffffu, sa1, off);
                sb0 += __shfl_xor_sync(0xffffffffu, sb0, off);
                sb1 += __shfl_xor_sync(0xffffffffu, sb1, off);
            }
            if (tig == 0) {
#pragma unroll
                for (int half = 0; half < 2; half++) {
                    int row = w * 32 + mt * 16 + gid + half * 8;
                    float o0 = (half ? sb0 : sa0) + b30;
                    float o1 = (half ? sb1 : sa1) + b31;
                    int pp = base + row;
                    int gg = pp / PTS_PER_G;
                    int rr = pp - gg * PTS_PER_G;
                    int ii = rr / JJ;
                    int jj = rr - ii * JJ;
                    size_t bofs = ((size_t)(gg * 2) * NPOS + ii) * JJ + jj;
                    g_bias[bofs] = o0;
                    g_bias[bofs + (size_t)NPOS * JJ] = o1;
                }
            }
        }
        __syncthreads();
    }
}

// ---------------- fused sim + bias + softmax + out (32 rows/block) ----------------
__global__ void attn_kernel() {
    const int h = blockIdx.y;
    const int i0 = blockIdx.x * 32;
    __shared__ float qs[32][65];
    __shared__ float ps[32][145];
    __shared__ float rsum[32];
    const int tid = threadIdx.x;  // 0..255

    for (int idx = tid; idx < 32 * 64; idx += 256) {
        int r = idx & 31, d = idx >> 5;
        int i = i0 + r;
        qs[r][d] = (i < NPOS) ? g_q[(size_t)(h * 64 + d) * NPOS + i] * SCALE : 0.f;
    }
    __syncthreads();

    for (int idx = tid; idx < 32 * JJ; idx += 256) {
        int r = idx / JJ, j = idx - r * JJ;
        int i = i0 + r;
        float s = 0.f;
#pragma unroll 8
        for (int d = 0; d < 64; d++)
            s += qs[r][d] * g_k[(size_t)(h * 64 + d) * JJ + j];
        if (i < NPOS) s += g_bias[((size_t)h * NPOS + i) * JJ + j];
        else s = 0.f;
        ps[r][j] = s;
    }
    __syncthreads();

    const int w = tid >> 5, lane = tid & 31;
#pragma unroll
    for (int rr = 0; rr < 4; rr++) {
        int row = w + rr * 8;
        float m = -1e30f;
        for (int j = lane; j < JJ; j += 32) m = fmaxf(m, ps[row][j]);
#pragma unroll
        for (int o = 16; o; o >>= 1) m = fmaxf(m, __shfl_xor_sync(0xffffffffu, m, o));
        float s = 0.f;
        for (int j = lane; j < JJ; j += 32) {
            float e = expf(ps[row][j] - m);
            ps[row][j] = e;
            s += e;
        }
#pragma unroll
        for (int o = 16; o; o >>= 1) s += __shfl_xor_sync(0xffffffffu, s, o);
        if (lane == 0) rsum[row] = s;
    }
    __syncthreads();

    for (int idx = tid; idx < 32 * 64; idx += 256) {
        int r = idx & 31, d = idx >> 5;
        int i = i0 + r;
        if (i >= NPOS) continue;
        const float* vrow = &g_v[(size_t)(h * 64 + d) * JJ];
        float o = 0.f;
#pragma unroll 8
        for (int j = 0; j < JJ; j++) o += ps[r][j] * vrow[j];
        g_ao[(size_t)(h * 64 + d) * NPOS + i] = o / rsum[r];
    }
}

// ---------------- cls passthrough ----------------
__global__ void cls_kernel(const float* __restrict__ x1, float* __restrict__ out) {
    int o = threadIdx.x;   // 256 threads
    out[(size_t)o * SEQ] = x1[(size_t)o * SEQ];
}

// ---------------- launcher ----------------
extern "C" void kernel_launch(void* const* d_in, const int* in_sizes, int n_in,
                              void* d_out, int out_size) {
    const float* x1    = (const float*)d_in[0];
    const float* x2    = (const float*)d_in[1];
    const float* w_off1= (const float*)d_in[2];
    const float* b_off1= (const float*)d_in[3];
    const float* w_off2= (const float*)d_in[4];
    const float* wq    = (const float*)d_in[5];
    const float* wk    = (const float*)d_in[6];
    const float* wv    = (const float*)d_in[7];
    const float* wout  = (const float*)d_in[8];
    const float* bout  = (const float*)d_in[9];
    const float* cpb_w1= (const float*)d_in[10];
    const float* cpb_b1= (const float*)d_in[11];
    const float* cpb_w2= (const float*)d_in[12];
    const float* cpb_b2= (const float*)d_in[13];
    const float* cpb_w3= (const float*)d_in[14];
    const float* cpb_b3= (const float*)d_in[15];
    float* out = (float*)d_out;

    float *qp, *kvp, *kp, *vp, *aop;
    cudaGetSymbolAddress((void**)&qp,  g_q);
    cudaGetSymbolAddress((void**)&kvp, g_kv);
    cudaGetSymbolAddress((void**)&kp,  g_k);
    cudaGetSymbolAddress((void**)&vp,  g_v);
    cudaGetSymbolAddress((void**)&aop, g_ao);

    // 1) q = wq @ f1   (512 x 2500, K=256)
    tf32gemm<<<dim3(40, 8), 256>>>(wq, x1, qp, INNER, NPOS, DIM, SEQ, 1, NPOS, 0, nullptr);

    // 2) depthwise conv + gelu
    dconv_kernel<<<INNER, JJ>>>(w_off1, b_off1);

    // 3) 1x1 conv + tanh + grid
    offgrid_kernel<<<G, JJ>>>(w_off2);

    // 4) bilinear sample
    gsample_kernel<<<G * JJ, 64>>>(x2);

    // 5) k, v GEMMs (512 x 144, K=256)
    tf32gemm<<<dim3(3, 8), 256>>>(wk, kvp, kp, INNER, JJ, DIM, JJ, 0, JJ, 0, nullptr);
    tf32gemm<<<dim3(3, 8), 256>>>(wv, kvp, vp, INNER, JJ, DIM, JJ, 0, JJ, 0, nullptr);

    // 6) CPB bias MLP on tensor cores (bf16, multi-tile)
    cpb_mma_kernel<<<CPB_BLOCKS, 128>>>(cpb_w1, cpb_b1, cpb_w2, cpb_b2,
                                        cpb_w3, cpb_b3);

    // 7) attention: sim + bias + softmax + out
    attn_kernel<<<dim3((NPOS + 31) / 32, HEADS), 256>>>();

    // 8) wout @ attn_out + bout -> output columns 1..2500
    tf32gemm<<<dim3(40, 4), 256>>>(wout, aop, out, DIM, NPOS, INNER, NPOS, 0, SEQ, 1, bout);

    // 9) cls token passthrough -> column 0
    cls_kernel<<<1, DIM>>>(x1, out);
}

// round 7
// speedup vs baseline: 4.2959x; 1.1982x over previous
#include <cuda_runtime.h>
#include <cuda_bf16.h>
#include <math.h>
#include <stdint.h>

// ---------------- problem constants ----------------
#define HH 50
#define WW 50
#define NPOS 2500          // H*W
#define DIM 256
#define HEADS 8
#define DH 64
#define G 4
#define INNER 512          // HEADS*DH
#define OFFD 128           // INNER/G
#define CPB 64             // DIM/4
#define O 2                // HEADS/G
#define KS 6
#define DF 4
#define PAD 1
#define HK 12
#define JJ 144             // HK*HK
#define SCALE 0.125f
#define OFF_SCALE 4.0f
#define SEQ 2501           // H*W+1
#define PTS_TOTAL (G * NPOS * JJ)   // 1,440,000
#define PTS_PER_G (NPOS * JJ)       // 360,000

// cpb tiling: 750 blocks x 15 iters x 128 points = 1,440,000
#define CPB_BLOCKS 750
#define CPB_ITERS 15
#define H1PAD 40
#define W2PAD 72

// ---------------- scratch (device globals, no allocation) ----------------
__device__ float g_q[INNER * NPOS];
__device__ float g_off1[INNER * JJ];
__device__ float g_vgs[G * JJ * 2];
__device__ float g_kv[DIM * JJ];
__device__ float g_k[INNER * JJ];
__device__ float g_v[INNER * JJ];
__device__ float g_bias[HEADS * NPOS * JJ];
__device__ float g_ao[INNER * NPOS];

// ---------------- mma helpers ----------------
__device__ __forceinline__ void mma_tf32(float* d, const uint32_t* a,
                                         uint32_t b0, uint32_t b1) {
    asm volatile(
        "mma.sync.aligned.m16n8k8.row.col.f32.tf32.tf32.f32 "
        "{%0,%1,%2,%3}, {%4,%5,%6,%7}, {%8,%9}, {%0,%1,%2,%3};\n"
        : "+f"(d[0]), "+f"(d[1]), "+f"(d[2]), "+f"(d[3])
        : "r"(a[0]), "r"(a[1]), "r"(a[2]), "r"(a[3]), "r"(b0), "r"(b1));
}

__device__ __forceinline__ void mma_bf16(float* d, const uint32_t* a,
                                         uint32_t b0, uint32_t b1) {
    asm volatile(
        "mma.sync.aligned.m16n8k16.row.col.f32.bf16.bf16.f32 "
        "{%0,%1,%2,%3}, {%4,%5,%6,%7}, {%8,%9}, {%0,%1,%2,%3};\n"
        : "+f"(d[0]), "+f"(d[1]), "+f"(d[2]), "+f"(d[3])
        : "r"(a[0]), "r"(a[1]), "r"(a[2]), "r"(a[3]), "r"(b0), "r"(b1));
}

__device__ __forceinline__ uint32_t f2tf32(float f) {
    uint32_t v;
    asm("cvt.rna.tf32.f32 %0, %1;" : "=r"(v) : "f"(f));
    return v;
}

__device__ __forceinline__ uint32_t pack_bf16x2(float lo, float hi) {
    __nv_bfloat162 p = __floats2bfloat162_rn(lo, hi);
    return *reinterpret_cast<uint32_t*>(&p);
}

// ---------------- 3xTF32 split-precision tensor-core GEMM ----------------
__global__ __launch_bounds__(256)
void tf32gemm(const float* __restrict__ A, const float* __restrict__ B,
              float* __restrict__ C, int M, int N, int K,
              int ldb, int boff, int ldc, int coff,
              const float* __restrict__ bias) {
    __shared__ uint32_t Ah[64][36], Al[64][36];
    __shared__ uint32_t Bh[32][72], Bl[32][72];
    const int tid = threadIdx.x;
    const int m0 = blockIdx.y * 64, n0 = blockIdx.x * 64;
    const int wid = tid >> 5, lane = tid & 31;
    const int gid = lane >> 2, tig = lane & 3;
    const int wm = (wid >> 1) * 16, wn = (wid & 1) * 32;

    float acc[4][4];
#pragma unroll
    for (int nt = 0; nt < 4; nt++)
#pragma unroll
        for (int c = 0; c < 4; c++) acc[nt][c] = 0.f;

    for (int k0 = 0; k0 < K; k0 += 32) {
        for (int idx = tid; idx < 2048; idx += 256) {
            int m = idx >> 5, k = idx & 31;
            float v = A[(size_t)(m0 + m) * K + k0 + k];
            uint32_t hi = f2tf32(v);
            Ah[m][k] = hi;
            Al[m][k] = f2tf32(v - __uint_as_float(hi));
        }
        for (int idx = tid; idx < 2048; idx += 256) {
            int k = idx >> 6, n = idx & 63;
            float v = (n0 + n < N) ? B[(size_t)(k0 + k) * ldb + boff + n0 + n] : 0.f;
            uint32_t hi = f2tf32(v);
            Bh[k][n] = hi;
            Bl[k][n] = f2tf32(v - __uint_as_float(hi));
        }
        __syncthreads();
#pragma unroll
        for (int ks = 0; ks < 32; ks += 8) {
            uint32_t ah[4], al[4];
            ah[0] = Ah[wm + gid][ks + tig];
            ah[1] = Ah[wm + gid + 8][ks + tig];
            ah[2] = Ah[wm + gid][ks + tig + 4];
            ah[3] = Ah[wm + gid + 8][ks + tig + 4];
            al[0] = Al[wm + gid][ks + tig];
            al[1] = Al[wm + gid + 8][ks + tig];
            al[2] = Al[wm + gid][ks + tig + 4];
            al[3] = Al[wm + gid + 8][ks + tig + 4];
#pragma unroll
            for (int nt = 0; nt < 4; nt++) {
                int nn = wn + nt * 8 + gid;
                uint32_t bh0 = Bh[ks + tig][nn], bh1 = Bh[ks + tig + 4][nn];
                uint32_t bl0 = Bl[ks + tig][nn], bl1 = Bl[ks + tig + 4][nn];
                mma_tf32(acc[nt], ah, bh0, bh1);
                mma_tf32(acc[nt], ah, bl0, bl1);
                mma_tf32(acc[nt], al, bh0, bh1);
            }
        }
        __syncthreads();
    }

    const int row0 = m0 + wm + gid;
    const float bb0 = bias ? bias[row0] : 0.f;
    const float bb1 = bias ? bias[row0 + 8] : 0.f;
#pragma unroll
    for (int nt = 0; nt < 4; nt++) {
        int col = n0 + wn + nt * 8 + 2 * tig;
        if (col < N) {
            C[(size_t)row0 * ldc + coff + col] = acc[nt][0] + bb0;
            C[(size_t)(row0 + 8) * ldc + coff + col] = acc[nt][2] + bb1;
        }
        if (col + 1 < N) {
            C[(size_t)row0 * ldc + coff + col + 1] = acc[nt][1] + bb0;
            C[(size_t)(row0 + 8) * ldc + coff + col + 1] = acc[nt][3] + bb1;
        }
    }
}

// ---------------- depthwise conv + bias + exact GELU ----------------
__global__ void dconv_kernel(const float* __restrict__ w1, const float* __restrict__ b1) {
    const int gc = blockIdx.x;
    const int c = gc & 127;
    const int j = threadIdx.x;
    const int oy = j / HK, ox = j % HK;
    const float* qrow = &g_q[(size_t)gc * NPOS];
    const float* wt = &w1[c * 36];
    float acc = 0.f;
#pragma unroll
    for (int ky = 0; ky < KS; ky++) {
        int iy = oy * DF - PAD + ky;
        if (iy < 0 || iy >= HH) continue;
#pragma unroll
        for (int kx = 0; kx < KS; kx++) {
            int ix = ox * DF - PAD + kx;
            if (ix < 0 || ix >= WW) continue;
            acc += qrow[iy * WW + ix] * wt[ky * KS + kx];
        }
    }
    float x = acc + b1[c];
    float gl = 0.5f * x * (1.0f + erff(x * 0.70710678118654752f));
    g_off1[(size_t)gc * JJ + j] = gl;
}

// ---------------- 1x1 conv + tanh*4 + grid ----------------
__global__ void offgrid_kernel(const float* __restrict__ w2) {
    const int g = blockIdx.x;
    const int j = threadIdx.x;
    float s0 = 0.f, s1 = 0.f;
    for (int c = 0; c < OFFD; c++) {
        float v = g_off1[(size_t)(g * OFFD + c) * JJ + j];
        s0 += w2[c] * v;
        s1 += w2[OFFD + c] * v;
    }
    float offx = tanhf(s0) * OFF_SCALE;
    float offy = tanhf(s1) * OFF_SCALE;
    int x = j % HK, y = j / HK;
    float vx = (float)x + offx;
    float vy = (float)y + offy;
    float sx = 2.0f * vx / (float)(HK - 1) - 1.0f;
    float sy = 2.0f * vy / (float)(HK - 1) - 1.0f;
    g_vgs[(g * JJ + j) * 2 + 0] = sx;
    g_vgs[(g * JJ + j) * 2 + 1] = sy;
}

// ---------------- bilinear grid sample ----------------
__global__ void gsample_kernel(const float* __restrict__ x2) {
    const int blk = blockIdx.x;
    const int g = blk / JJ;
    const int j = blk % JJ;
    const int c = threadIdx.x;
    float sx = g_vgs[(g * JJ + j) * 2 + 0];
    float sy = g_vgs[(g * JJ + j) * 2 + 1];
    float x = (sx + 1.0f) * (WW * 0.5f) - 0.5f;
    float y = (sy + 1.0f) * (HH * 0.5f) - 0.5f;
    float x0f = floorf(x), y0f = floorf(y);
    int x0 = (int)x0f, y0 = (int)y0f;
    float wx1 = x - x0f, wy1 = y - y0f;
    float wx0 = 1.0f - wx1, wy0 = 1.0f - wy1;
    const float* img = &x2[(size_t)(g * (DIM / G) + c) * SEQ + 1];
    float acc = 0.f;
#pragma unroll
    for (int dy = 0; dy < 2; dy++) {
#pragma unroll
        for (int dx = 0; dx < 2; dx++) {
            int ix = x0 + dx, iy = y0 + dy;
            float w = (dx ? wx1 : wx0) * (dy ? wy1 : wy0);
            if (ix >= 0 && ix < WW && iy >= 0 && iy < HH)
                acc += img[iy * WW + ix] * w;
        }
    }
    g_kv[(size_t)(g * (DIM / G) + c) * JJ + j] = acc;
}

// ---------------- CPB bias MLP: bf16 mma, W2 fragments in registers ----------------
__global__ __launch_bounds__(128)
void cpb_mma_kernel(const float* __restrict__ W1, const float* __restrict__ B1,
                    const float* __restrict__ W2, const float* __restrict__ B2,
                    const float* __restrict__ W3, const float* __restrict__ B3) {
    __shared__ uint32_t H1s[128][H1PAD];
    __shared__ uint32_t W2s[32][W2PAD];
    __shared__ float W1s[128], B1s[64], B2s[64], W3s[128];

    const int t = threadIdx.x;

    for (int idx = t; idx < 32 * 64; idx += 128) {
        int kk = idx >> 6, n = idx & 63;
        W2s[kk][n] = pack_bf16x2(W2[(2 * kk) * 64 + n], W2[(2 * kk + 1) * 64 + n]);
    }
    if (t < 128) W1s[t] = W1[t];
    if (t < 64) { B1s[t] = B1[t]; B2s[t] = B2[t]; }
    if (t < 128) W3s[t] = W3[t];
    __syncthreads();

    const int w = t >> 5, lane = t & 31;
    const int gid = lane >> 2, tig = lane & 3;
    const int r0 = w * 32 + gid;
    const float b30 = B3[0], b31 = B3[1];

    // hoist W2 B-fragments to registers once per block
    uint32_t bw0[4][8], bw1[4][8];
#pragma unroll
    for (int ks = 0; ks < 4; ks++)
#pragma unroll
        for (int nt = 0; nt < 8; nt++) {
            bw0[ks][nt] = W2s[ks * 8 + tig][nt * 8 + gid];
            bw1[ks][nt] = W2s[ks * 8 + tig + 4][nt * 8 + gid];
        }

    for (int it = 0; it < CPB_ITERS; it++) {
        const int base = (blockIdx.x * CPB_ITERS + it) * 128;

        {
            const int p = base + t;
            const int g = p / PTS_PER_G;
            const int rem = p - g * PTS_PER_G;
            const int i = rem / JJ;
            const int j = rem - i * JJ;
            const float gqx = 2.0f * (float)(i % WW) / (float)(WW - 1) - 1.0f;
            const float gqy = 2.0f * (float)(i / WW) / (float)(HH - 1) - 1.0f;
            const float px = gqx - g_vgs[(g * JJ + j) * 2 + 0];
            const float py = gqy - g_vgs[(g * JJ + j) * 2 + 1];
            const float fx = copysignf(log1pf(fabsf(px)), px);
            const float fy = copysignf(log1pf(fabsf(py)), py);
            float h[64];
#pragma unroll
            for (int m = 0; m < 64; m++)
                h[m] = fmaxf(fmaf(fx, W1s[m], fmaf(fy, W1s[64 + m], B1s[m])), 0.f);
#pragma unroll
            for (int kk = 0; kk < 32; kk++)
                H1s[t][kk] = pack_bf16x2(h[2 * kk], h[2 * kk + 1]);
        }
        __syncthreads();

        float acc[2][8][4];
#pragma unroll
        for (int mt = 0; mt < 2; mt++)
#pragma unroll
            for (int nt = 0; nt < 8; nt++)
#pragma unroll
                for (int c = 0; c < 4; c++) acc[mt][nt][c] = 0.f;

#pragma unroll
        for (int ks = 0; ks < 4; ks++) {
            const int kk0 = ks * 8;
            uint32_t a[2][4];
#pragma unroll
            for (int mt = 0; mt < 2; mt++) {
                a[mt][0] = H1s[r0 + mt * 16][kk0 + tig];
                a[mt][1] = H1s[r0 + mt * 16 + 8][kk0 + tig];
                a[mt][2] = H1s[r0 + mt * 16][kk0 + tig + 4];
                a[mt][3] = H1s[r0 + mt * 16 + 8][kk0 + tig + 4];
            }
#pragma unroll
            for (int nt = 0; nt < 8; nt++) {
                mma_bf16(acc[0][nt], a[0], bw0[ks][nt], bw1[ks][nt]);
                mma_bf16(acc[1][nt], a[1], bw0[ks][nt], bw1[ks][nt]);
            }
        }

#pragma unroll
        for (int mt = 0; mt < 2; mt++) {
            float sa0 = 0.f, sa1 = 0.f;
            float sb0 = 0.f, sb1 = 0.f;
#pragma unroll
            for (int nt = 0; nt < 8; nt++) {
                int n0 = nt * 8 + 2 * tig;
                int n1 = n0 + 1;
                float h;
                h = fmaxf(acc[mt][nt][0] + B2s[n0], 0.f);
                sa0 += h * W3s[2 * n0]; sa1 += h * W3s[2 * n0 + 1];
                h = fmaxf(acc[mt][nt][1] + B2s[n1], 0.f);
                sa0 += h * W3s[2 * n1]; sa1 += h * W3s[2 * n1 + 1];
                h = fmaxf(acc[mt][nt][2] + B2s[n0], 0.f);
                sb0 += h * W3s[2 * n0]; sb1 += h * W3s[2 * n0 + 1];
                h = fmaxf(acc[mt][nt][3] + B2s[n1], 0.f);
                sb0 += h * W3s[2 * n1]; sb1 += h * W3s[2 * n1 + 1];
            }
#pragma unroll
            for (int off = 1; off <= 2; off <<= 1) {
                sa0 += __shfl_xor_sync(0xffffffffu, sa0, off);
                sa1 += __shfl_xor_sync(0xffffffffu, sa1, off);
                sb0 += __shfl_xor_sync(0xffffffffu, sb0, off);
                sb1 += __shfl_xor_sync(0xffffffffu, sb1, off);
            }
            if (tig == 0) {
#pragma unroll
                for (int half = 0; half < 2; half++) {
                    int row = w * 32 + mt * 16 + gid + half * 8;
                    float o0 = (half ? sb0 : sa0) + b30;
                    float o1 = (half ? sb1 : sa1) + b31;
                    int pp = base + row;
                    int gg = pp / PTS_PER_G;
                    int rr = pp - gg * PTS_PER_G;
                    int ii = rr / JJ;
                    int jj = rr - ii * JJ;
                    size_t bofs = ((size_t)(gg * 2) * NPOS + ii) * JJ + jj;
                    g_bias[bofs] = o0;
                    g_bias[bofs + (size_t)NPOS * JJ] = o1;
                }
            }
        }
        __syncthreads();
    }
}

// ---------------- fused sim + bias + softmax + out (vectorized) ----------------
__global__ void attn_kernel() {
    const int h = blockIdx.y;
    const int i0 = blockIdx.x * 32;
    __shared__ float qs[32][65];
    __shared__ float4 ps4[32][37];   // row stride 148 floats; conflict-free phases
    __shared__ float rsum[32];
    const int tid = threadIdx.x;  // 0..255

    // q load (coalesced over i)
    for (int idx = tid; idx < 32 * 64; idx += 256) {
        int r = idx & 31, d = idx >> 5;
        int i = i0 + r;
        qs[r][d] = (i < NPOS) ? g_q[(size_t)(h * 64 + d) * NPOS + i] * SCALE : 0.f;
    }
    __syncthreads();

    // sim + bias: thread handles 4 rows x 4 j per item; 8 rg x 36 j4 items
    const float4* k4 = reinterpret_cast<const float4*>(g_k + (size_t)h * 64 * JJ);
    for (int idx = tid; idx < 8 * 36; idx += 256) {
        int rg = idx / 36, j4 = idx - rg * 36;
        float4 s0 = {0, 0, 0, 0}, s1 = {0, 0, 0, 0}, s2 = {0, 0, 0, 0}, s3 = {0, 0, 0, 0};
#pragma unroll 16
        for (int d = 0; d < 64; d++) {
            float4 kv = k4[d * 36 + j4];
            float q0 = qs[rg * 4 + 0][d], q1 = qs[rg * 4 + 1][d];
            float q2 = qs[rg * 4 + 2][d], q3 = qs[rg * 4 + 3][d];
            s0.x = fmaf(q0, kv.x, s0.x); s0.y = fmaf(q0, kv.y, s0.y);
            s0.z = fmaf(q0, kv.z, s0.z); s0.w = fmaf(q0, kv.w, s0.w);
            s1.x = fmaf(q1, kv.x, s1.x); s1.y = fmaf(q1, kv.y, s1.y);
            s1.z = fmaf(q1, kv.z, s1.z); s1.w = fmaf(q1, kv.w, s1.w);
            s2.x = fmaf(q2, kv.x, s2.x); s2.y = fmaf(q2, kv.y, s2.y);
            s2.z = fmaf(q2, kv.z, s2.z); s2.w = fmaf(q2, kv.w, s2.w);
            s3.x = fmaf(q3, kv.x, s3.x); s3.y = fmaf(q3, kv.y, s3.y);
            s3.z = fmaf(q3, kv.z, s3.z); s3.w = fmaf(q3, kv.w, s3.w);
        }
        float4 sv[4] = {s0, s1, s2, s3};
#pragma unroll
        for (int u = 0; u < 4; u++) {
            int r = rg * 4 + u, i = i0 + r;
            if (i < NPOS) {
                const float4 b = *reinterpret_cast<const float4*>(
                    &g_bias[((size_t)h * NPOS + i) * JJ + 4 * j4]);
                sv[u].x += b.x; sv[u].y += b.y; sv[u].z += b.z; sv[u].w += b.w;
            }
            ps4[r][j4] = sv[u];
        }
    }
    __syncthreads();

    // softmax: warp w owns rows {w, w+8, w+16, w+24}
    float* ps = reinterpret_cast<float*>(ps4);
    const int w = tid >> 5, lane = tid & 31;
#pragma unroll
    for (int rr = 0; rr < 4; rr++) {
        int row = w + rr * 8;
        float* pr = ps + row * 148;
        float m = -1e30f;
        for (int j = lane; j < JJ; j += 32) m = fmaxf(m, pr[j]);
#pragma unroll
        for (int o = 16; o; o >>= 1) m = fmaxf(m, __shfl_xor_sync(0xffffffffu, m, o));
        float s = 0.f;
        for (int j = lane; j < JJ; j += 32) {
            float e = expf(pr[j] - m);
            pr[j] = e;
            s += e;
        }
#pragma unroll
        for (int o = 16; o; o >>= 1) s += __shfl_xor_sync(0xffffffffu, s, o);
        if (lane == 0) rsum[row] = s;
    }
    __syncthreads();

    // out: thread handles 4 d x 1 r; lanes span r -> coalesced stores, uniform v loads
    const float4* v4 = reinterpret_cast<const float4*>(g_v + (size_t)h * 64 * JJ);
    for (int idx = tid; idx < 16 * 32; idx += 256) {
        int dg = idx >> 5, r = idx & 31;
        int i = i0 + r;
        if (i >= NPOS) continue;
        float o0 = 0.f, o1 = 0.f, o2 = 0.f, o3 = 0.f;
#pragma unroll 4
        for (int j4 = 0; j4 < 36; j4++) {
            float4 pv = ps4[r][j4];
            float4 v0 = v4[(dg * 4 + 0) * 36 + j4];
            float4 v1 = v4[(dg * 4 + 1) * 36 + j4];
            float4 v2 = v4[(dg * 4 + 2) * 36 + j4];
            float4 v3 = v4[(dg * 4 + 3) * 36 + j4];
            o0 += pv.x * v0.x + pv.y * v0.y + pv.z * v0.z + pv.w * v0.w;
            o1 += pv.x * v1.x + pv.y * v1.y + pv.z * v1.z + pv.w * v1.w;
            o2 += pv.x * v2.x + pv.y * v2.y + pv.z * v2.z + pv.w * v2.w;
            o3 += pv.x * v3.x + pv.y * v3.y + pv.z * v3.z + pv.w * v3.w;
        }
        float inv = 1.0f / rsum[r];
        g_ao[(size_t)(h * 64 + dg * 4 + 0) * NPOS + i] = o0 * inv;
        g_ao[(size_t)(h * 64 + dg * 4 + 1) * NPOS + i] = o1 * inv;
        g_ao[(size_t)(h * 64 + dg * 4 + 2) * NPOS + i] = o2 * inv;
        g_ao[(size_t)(h * 64 + dg * 4 + 3) * NPOS + i] = o3 * inv;
    }
}

// ---------------- cls passthrough ----------------
__global__ void cls_kernel(const float* __restrict__ x1, float* __restrict__ out) {
    int o = threadIdx.x;
    out[(size_t)o * SEQ] = x1[(size_t)o * SEQ];
}

// ---------------- launcher ----------------
extern "C" void kernel_launch(void* const* d_in, const int* in_sizes, int n_in,
                              void* d_out, int out_size) {
    const float* x1    = (const float*)d_in[0];
    const float* x2    = (const float*)d_in[1];
    const float* w_off1= (const float*)d_in[2];
    const float* b_off1= (const float*)d_in[3];
    const float* w_off2= (const float*)d_in[4];
    const float* wq    = (const float*)d_in[5];
    const float* wk    = (const float*)d_in[6];
    const float* wv    = (const float*)d_in[7];
    const float* wout  = (const float*)d_in[8];
    const float* bout  = (const float*)d_in[9];
    const float* cpb_w1= (const float*)d_in[10];
    const float* cpb_b1= (const float*)d_in[11];
    const float* cpb_w2= (const float*)d_in[12];
    const float* cpb_b2= (const float*)d_in[13];
    const float* cpb_w3= (const float*)d_in[14];
    const float* cpb_b3= (const float*)d_in[15];
    float* out = (float*)d_out;

    float *qp, *kvp, *kp, *vp, *aop;
    cudaGetSymbolAddress((void**)&qp,  g_q);
    cudaGetSymbolAddress((void**)&kvp, g_kv);
    cudaGetSymbolAddress((void**)&kp,  g_k);
    cudaGetSymbolAddress((void**)&vp,  g_v);
    cudaGetSymbolAddress((void**)&aop, g_ao);

    // 1) q = wq @ f1
    tf32gemm<<<dim3(40, 8), 256>>>(wq, x1, qp, INNER, NPOS, DIM, SEQ, 1, NPOS, 0, nullptr);

    // 2) depthwise conv + gelu
    dconv_kernel<<<INNER, JJ>>>(w_off1, b_off1);

    // 3) 1x1 conv + tanh + grid
    offgrid_kernel<<<G, JJ>>>(w_off2);

    // 4) bilinear sample
    gsample_kernel<<<G * JJ, 64>>>(x2);

    // 5) k, v GEMMs
    tf32gemm<<<dim3(3, 8), 256>>>(wk, kvp, kp, INNER, JJ, DIM, JJ, 0, JJ, 0, nullptr);
    tf32gemm<<<dim3(3, 8), 256>>>(wv, kvp, vp, INNER, JJ, DIM, JJ, 0, JJ, 0, nullptr);

    // 6) CPB bias MLP
    cpb_mma_kernel<<<CPB_BLOCKS, 128>>>(cpb_w1, cpb_b1, cpb_w2, cpb_b2,
                                        cpb_w3, cpb_b3);

    // 7) attention
    attn_kernel<<<dim3((NPOS + 31) / 32, HEADS), 256>>>();

    // 8) wout @ attn_out + bout
    tf32gemm<<<dim3(40, 4), 256>>>(wout, aop, out, DIM, NPOS, INNER, NPOS, 0, SEQ, 1, bout);

    // 9) cls token passthrough
    cls_kernel<<<1, DIM>>>(x1, out);
}

// round 8
// speedup vs baseline: 4.4074x; 1.0260x over previous
#include <cuda_runtime.h>
#include <cuda_bf16.h>
#include <math.h>
#include <stdint.h>

// ---------------- problem constants ----------------
#define HH 50
#define WW 50
#define NPOS 2500          // H*W
#define DIM 256
#define HEADS 8
#define DH 64
#define G 4
#define INNER 512          // HEADS*DH
#define OFFD 128           // INNER/G
#define CPB 64             // DIM/4
#define O 2                // HEADS/G
#define KS 6
#define DF 4
#define PAD 1
#define HK 12
#define JJ 144             // HK*HK
#define SCALE 0.125f
#define OFF_SCALE 4.0f
#define SEQ 2501           // H*W+1
#define PTS_TOTAL (G * NPOS * JJ)   // 1,440,000
#define PTS_PER_G (NPOS * JJ)       // 360,000

#define CPB_BLOCKS 750
#define CPB_ITERS 15
#define H1PAD 40

// ---------------- scratch (device globals, no allocation) ----------------
__device__ float g_q[INNER * NPOS];
__device__ float g_off1[INNER * JJ];
__device__ float g_vgs[G * JJ * 2];
__device__ float g_kv[DIM * JJ];
__device__ float g_k[INNER * JJ];
__device__ float g_v[INNER * JJ];
__device__ float g_bias[HEADS * NPOS * JJ];
__device__ float g_ao[INNER * NPOS];

// ---------------- helpers ----------------
__device__ __forceinline__ void mma_tf32(float* d, const uint32_t* a,
                                         uint32_t b0, uint32_t b1) {
    asm volatile(
        "mma.sync.aligned.m16n8k8.row.col.f32.tf32.tf32.f32 "
        "{%0,%1,%2,%3}, {%4,%5,%6,%7}, {%8,%9}, {%0,%1,%2,%3};\n"
        : "+f"(d[0]), "+f"(d[1]), "+f"(d[2]), "+f"(d[3])
        : "r"(a[0]), "r"(a[1]), "r"(a[2]), "r"(a[3]), "r"(b0), "r"(b1));
}

__device__ __forceinline__ void mma_bf16(float* d, const uint32_t* a,
                                         uint32_t b0, uint32_t b1) {
    asm volatile(
        "mma.sync.aligned.m16n8k16.row.col.f32.bf16.bf16.f32 "
        "{%0,%1,%2,%3}, {%4,%5,%6,%7}, {%8,%9}, {%0,%1,%2,%3};\n"
        : "+f"(d[0]), "+f"(d[1]), "+f"(d[2]), "+f"(d[3])
        : "r"(a[0]), "r"(a[1]), "r"(a[2]), "r"(a[3]), "r"(b0), "r"(b1));
}

__device__ __forceinline__ uint32_t f2tf32(float f) {
    uint32_t v;
    asm("cvt.rna.tf32.f32 %0, %1;" : "=r"(v) : "f"(f));
    return v;
}

__device__ __forceinline__ uint32_t pack_bf16x2(float lo, float hi) {
    __nv_bfloat162 p = __floats2bfloat162_rn(lo, hi);
    return *reinterpret_cast<uint32_t*>(&p);
}

// relu(fx*wx + fy*wy + bb) in bf16x2
__device__ __forceinline__ uint32_t h1_bf16x2(__nv_bfloat162 fx2, __nv_bfloat162 fy2,
                                              uint32_t wx, uint32_t wy, uint32_t bb) {
    __nv_bfloat162 r = __hfma2(fy2, *reinterpret_cast<__nv_bfloat162*>(&wy),
                               *reinterpret_cast<__nv_bfloat162*>(&bb));
    r = __hfma2(fx2, *reinterpret_cast<__nv_bfloat162*>(&wx), r);
    __nv_bfloat162 z = __floats2bfloat162_rn(0.f, 0.f);
    r = __hmax2(r, z);
    return *reinterpret_cast<uint32_t*>(&r);
}

// polynomial exp (FMA pipe; avoids MUFU throughput wall)
__device__ __forceinline__ float fast_exp(float x) {
    x = fmaxf(x, -80.f);
    float t = x * 1.4426950408889634f;     // log2(e)
    float fl = rintf(t);
    float f = t - fl;                      // [-0.5, 0.5]
    float p = 1.33335581e-3f;
    p = fmaf(p, f, 9.61812911e-3f);
    p = fmaf(p, f, 5.55041087e-2f);
    p = fmaf(p, f, 2.40226507e-1f);
    p = fmaf(p, f, 6.93147180e-1f);
    p = fmaf(p, f, 1.0f);
    int e = (int)fl;
    return p * __int_as_float((e + 127) << 23);
}

// ---------------- 3xTF32 split-precision tensor-core GEMM ----------------
// blockIdx.z == 1 -> use (A2, C2) instead (merged k/v launch)
__global__ __launch_bounds__(256)
void tf32gemm(const float* __restrict__ A, const float* __restrict__ B,
              float* __restrict__ C, int M, int N, int K,
              int ldb, int boff, int ldc, int coff,
              const float* __restrict__ bias,
              const float* __restrict__ A2, float* __restrict__ C2) {
    __shared__ uint32_t Ah[64][36], Al[64][36];
    __shared__ uint32_t Bh[32][72], Bl[32][72];
    const float* Ause = A;
    float* Cuse = C;
    if (blockIdx.z) { Ause = A2; Cuse = C2; }
    const int tid = threadIdx.x;
    const int m0 = blockIdx.y * 64, n0 = blockIdx.x * 64;
    const int wid = tid >> 5, lane = tid & 31;
    const int gid = lane >> 2, tig = lane & 3;
    const int wm = (wid >> 1) * 16, wn = (wid & 1) * 32;

    float acc[4][4];
#pragma unroll
    for (int nt = 0; nt < 4; nt++)
#pragma unroll
        for (int c = 0; c < 4; c++) acc[nt][c] = 0.f;

    for (int k0 = 0; k0 < K; k0 += 32) {
        for (int idx = tid; idx < 2048; idx += 256) {
            int m = idx >> 5, k = idx & 31;
            float v = Ause[(size_t)(m0 + m) * K + k0 + k];
            uint32_t hi = f2tf32(v);
            Ah[m][k] = hi;
            Al[m][k] = f2tf32(v - __uint_as_float(hi));
        }
        for (int idx = tid; idx < 2048; idx += 256) {
            int k = idx >> 6, n = idx & 63;
            float v = (n0 + n < N) ? B[(size_t)(k0 + k) * ldb + boff + n0 + n] : 0.f;
            uint32_t hi = f2tf32(v);
            Bh[k][n] = hi;
            Bl[k][n] = f2tf32(v - __uint_as_float(hi));
        }
        __syncthreads();
#pragma unroll
        for (int ks = 0; ks < 32; ks += 8) {
            uint32_t ah[4], al[4];
            ah[0] = Ah[wm + gid][ks + tig];
            ah[1] = Ah[wm + gid + 8][ks + tig];
            ah[2] = Ah[wm + gid][ks + tig + 4];
            ah[3] = Ah[wm + gid + 8][ks + tig + 4];
            al[0] = Al[wm + gid][ks + tig];
            al[1] = Al[wm + gid + 8][ks + tig];
            al[2] = Al[wm + gid][ks + tig + 4];
            al[3] = Al[wm + gid + 8][ks + tig + 4];
#pragma unroll
            for (int nt = 0; nt < 4; nt++) {
                int nn = wn + nt * 8 + gid;
                uint32_t bh0 = Bh[ks + tig][nn], bh1 = Bh[ks + tig + 4][nn];
                uint32_t bl0 = Bl[ks + tig][nn], bl1 = Bl[ks + tig + 4][nn];
                mma_tf32(acc[nt], ah, bh0, bh1);
                mma_tf32(acc[nt], ah, bl0, bl1);
                mma_tf32(acc[nt], al, bh0, bh1);
            }
        }
        __syncthreads();
    }

    const int row0 = m0 + wm + gid;
    const float bb0 = bias ? bias[row0] : 0.f;
    const float bb1 = bias ? bias[row0 + 8] : 0.f;
#pragma unroll
    for (int nt = 0; nt < 4; nt++) {
        int col = n0 + wn + nt * 8 + 2 * tig;
        if (col < N) {
            Cuse[(size_t)row0 * ldc + coff + col] = acc[nt][0] + bb0;
            Cuse[(size_t)(row0 + 8) * ldc + coff + col] = acc[nt][2] + bb1;
        }
        if (col + 1 < N) {
            Cuse[(size_t)row0 * ldc + coff + col + 1] = acc[nt][1] + bb0;
            Cuse[(size_t)(row0 + 8) * ldc + coff + col + 1] = acc[nt][3] + bb1;
        }
    }
}

// ---------------- depthwise conv + bias + GELU (+ folded cls copy) ----------------
__global__ void dconv_kernel(const float* __restrict__ w1, const float* __restrict__ b1,
                             const float* __restrict__ x1, float* __restrict__ out) {
    const int gc = blockIdx.x;
    const int c = gc & 127;
    const int j = threadIdx.x;
    // folded cls passthrough (independent work, block 0 only)
    if (gc == 0) {
        for (int o = j; o < DIM; o += JJ)
            out[(size_t)o * SEQ] = x1[(size_t)o * SEQ];
    }
    const int oy = j / HK, ox = j % HK;
    const float* qrow = &g_q[(size_t)gc * NPOS];
    const float* wt = &w1[c * 36];
    float acc = 0.f;
#pragma unroll
    for (int ky = 0; ky < KS; ky++) {
        int iy = oy * DF - PAD + ky;
        if (iy < 0 || iy >= HH) continue;
#pragma unroll
        for (int kx = 0; kx < KS; kx++) {
            int ix = ox * DF - PAD + kx;
            if (ix < 0 || ix >= WW) continue;
            acc += qrow[iy * WW + ix] * wt[ky * KS + kx];
        }
    }
    float x = acc + b1[c];
    float gl = 0.5f * x * (1.0f + erff(x * 0.70710678118654752f));
    g_off1[(size_t)gc * JJ + j] = gl;
}

// ---------------- 1x1 conv + tanh*4 + grid ----------------
__global__ void offgrid_kernel(const float* __restrict__ w2) {
    const int g = blockIdx.x;
    const int j = threadIdx.x;
    float s0 = 0.f, s1 = 0.f;
    for (int c = 0; c < OFFD; c++) {
        float v = g_off1[(size_t)(g * OFFD + c) * JJ + j];
        s0 += w2[c] * v;
        s1 += w2[OFFD + c] * v;
    }
    float offx = tanhf(s0) * OFF_SCALE;
    float offy = tanhf(s1) * OFF_SCALE;
    int x = j % HK, y = j / HK;
    float vx = (float)x + offx;
    float vy = (float)y + offy;
    float sx = 2.0f * vx / (float)(HK - 1) - 1.0f;
    float sy = 2.0f * vy / (float)(HK - 1) - 1.0f;
    g_vgs[(g * JJ + j) * 2 + 0] = sx;
    g_vgs[(g * JJ + j) * 2 + 1] = sy;
}

// ---------------- bilinear grid sample ----------------
__global__ void gsample_kernel(const float* __restrict__ x2) {
    const int blk = blockIdx.x;
    const int g = blk / JJ;
    const int j = blk % JJ;
    const int c = threadIdx.x;
    float sx = g_vgs[(g * JJ + j) * 2 + 0];
    float sy = g_vgs[(g * JJ + j) * 2 + 1];
    float x = (sx + 1.0f) * (WW * 0.5f) - 0.5f;
    float y = (sy + 1.0f) * (HH * 0.5f) - 0.5f;
    float x0f = floorf(x), y0f = floorf(y);
    int x0 = (int)x0f, y0 = (int)y0f;
    float wx1 = x - x0f, wy1 = y - y0f;
    float wx0 = 1.0f - wx1, wy0 = 1.0f - wy1;
    const float* img = &x2[(size_t)(g * (DIM / G) + c) * SEQ + 1];
    float acc = 0.f;
#pragma unroll
    for (int dy = 0; dy < 2; dy++) {
#pragma unroll
        for (int dx = 0; dx < 2; dx++) {
            int ix = x0 + dx, iy = y0 + dy;
            float w = (dx ? wx1 : wx0) * (dy ? wy1 : wy0);
            if (ix >= 0 && ix < WW && iy >= 0 && iy < HH)
                acc += img[iy * WW + ix] * w;
        }
    }
    g_kv[(size_t)(g * (DIM / G) + c) * JJ + j] = acc;
}

// ---------------- CPB bias MLP: bf16x2 layer1 + bf16 mma layer2 ----------------
__global__ __launch_bounds__(128)
void cpb_mma_kernel(const float* __restrict__ W1, const float* __restrict__ B1,
                    const float* __restrict__ W2, const float* __restrict__ B2,
                    const float* __restrict__ W3, const float* __restrict__ B3) {
    __shared__ uint32_t H1s[128][H1PAD];
    __shared__ uint32_t W2s[32][72];
    __shared__ __align__(16) uint32_t Wx2s[32], Wy2s[32], Bb2s[32];
    __shared__ float B2s[64], W3s[128];
    __shared__ float vgss[G * JJ * 2];   // staged sampling grid (4.6KB)

    const int t = threadIdx.x;

    for (int idx = t; idx < 32 * 64; idx += 128) {
        int kk = idx >> 6, n = idx & 63;
        W2s[kk][n] = pack_bf16x2(W2[(2 * kk) * 64 + n], W2[(2 * kk + 1) * 64 + n]);
    }
    if (t < 32) {
        Wx2s[t] = pack_bf16x2(W1[2 * t], W1[2 * t + 1]);
        Wy2s[t] = pack_bf16x2(W1[64 + 2 * t], W1[64 + 2 * t + 1]);
        Bb2s[t] = pack_bf16x2(B1[2 * t], B1[2 * t + 1]);
    }
    if (t < 64) B2s[t] = B2[t];
    W3s[t] = W3[t];
    for (int idx = t; idx < G * JJ * 2; idx += 128) vgss[idx] = g_vgs[idx];
    __syncthreads();

    const int w = t >> 5, lane = t & 31;
    const int gid = lane >> 2, tig = lane & 3;
    const int r0 = w * 32 + gid;
    const float b30 = B3[0], b31 = B3[1];

    // W2 B-fragments in registers (once per block)
    uint32_t bw0[4][8], bw1[4][8];
#pragma unroll
    for (int ks = 0; ks < 4; ks++)
#pragma unroll
        for (int nt = 0; nt < 8; nt++) {
            bw0[ks][nt] = W2s[ks * 8 + tig][nt * 8 + gid];
            bw1[ks][nt] = W2s[ks * 8 + tig + 4][nt * 8 + gid];
        }

    // incremental point decomposition for this thread's layer-1 point
    const int base0 = blockIdx.x * CPB_ITERS * 128;
    int p = base0 + t;
    int gg = p / PTS_PER_G;
    int rem = p - gg * PTS_PER_G;
    int ii = rem / JJ;
    int jj = rem - ii * JJ;
    int ix = ii % WW, iy = ii / WW;

    const uint4* wx4 = reinterpret_cast<const uint4*>(Wx2s);
    const uint4* wy4 = reinterpret_cast<const uint4*>(Wy2s);
    const uint4* bb4 = reinterpret_cast<const uint4*>(Bb2s);

    for (int it = 0; it < CPB_ITERS; it++) {
        const int base = base0 + it * 128;

        // --- layer 1 in bf16x2 ---
        {
            const float gqx = (float)ix * (2.0f / (WW - 1)) - 1.0f;
            const float gqy = (float)iy * (2.0f / (HH - 1)) - 1.0f;
            const float px = gqx - vgss[(gg * JJ + jj) * 2 + 0];
            const float py = gqy - vgss[(gg * JJ + jj) * 2 + 1];
            const float fx = copysignf(log1pf(fabsf(px)), px);
            const float fy = copysignf(log1pf(fabsf(py)), py);
            __nv_bfloat162 fx2 = __floats2bfloat162_rn(fx, fx);
            __nv_bfloat162 fy2 = __floats2bfloat162_rn(fy, fy);
            uint4* h1row = reinterpret_cast<uint4*>(&H1s[t][0]);
#pragma unroll
            for (int q = 0; q < 8; q++) {
                uint4 wx = wx4[q], wy = wy4[q], bb = bb4[q];
                uint4 hv;
                hv.x = h1_bf16x2(fx2, fy2, wx.x, wy.x, bb.x);
                hv.y = h1_bf16x2(fx2, fy2, wx.y, wy.y, bb.y);
                hv.z = h1_bf16x2(fx2, fy2, wx.z, wy.z, bb.z);
                hv.w = h1_bf16x2(fx2, fy2, wx.w, wy.w, bb.w);
                h1row[q] = hv;
            }
            // advance point by 128
            jj += 128;
            if (jj >= JJ) {
                jj -= JJ;
                ii++; ix++;
                if (ix == WW) { ix = 0; iy++; }
                if (ii == NPOS) { ii = 0; ix = 0; iy = 0; gg++; }
            }
        }
        __syncthreads();

        // --- layer 2 via bf16 mma ---
        float acc[2][8][4];
#pragma unroll
        for (int mt = 0; mt < 2; mt++)
#pragma unroll
            for (int nt = 0; nt < 8; nt++)
#pragma unroll
                for (int c = 0; c < 4; c++) acc[mt][nt][c] = 0.f;

#pragma unroll
        for (int ks = 0; ks < 4; ks++) {
            const int kk0 = ks * 8;
            uint32_t a[2][4];
#pragma unroll
            for (int mt = 0; mt < 2; mt++) {
                a[mt][0] = H1s[r0 + mt * 16][kk0 + tig];
                a[mt][1] = H1s[r0 + mt * 16 + 8][kk0 + tig];
                a[mt][2] = H1s[r0 + mt * 16][kk0 + tig + 4];
                a[mt][3] = H1s[r0 + mt * 16 + 8][kk0 + tig + 4];
            }
#pragma unroll
            for (int nt = 0; nt < 8; nt++) {
                mma_bf16(acc[0][nt], a[0], bw0[ks][nt], bw1[ks][nt]);
                mma_bf16(acc[1][nt], a[1], bw0[ks][nt], bw1[ks][nt]);
            }
        }

        // --- epilogue ---
#pragma unroll
        for (int mt = 0; mt < 2; mt++) {
            float sa0 = 0.f, sa1 = 0.f;
            float sb0 = 0.f, sb1 = 0.f;
#pragma unroll
            for (int nt = 0; nt < 8; nt++) {
                int n0 = nt * 8 + 2 * tig;
                int n1 = n0 + 1;
                float h;
                h = fmaxf(acc[mt][nt][0] + B2s[n0], 0.f);
                sa0 += h * W3s[2 * n0]; sa1 += h * W3s[2 * n0 + 1];
                h = fmaxf(acc[mt][nt][1] + B2s[n1], 0.f);
                sa0 += h * W3s[2 * n1]; sa1 += h * W3s[2 * n1 + 1];
                h = fmaxf(acc[mt][nt][2] + B2s[n0], 0.f);
                sb0 += h * W3s[2 * n0]; sb1 += h * W3s[2 * n0 + 1];
                h = fmaxf(acc[mt][nt][3] + B2s[n1], 0.f);
                sb0 += h * W3s[2 * n1]; sb1 += h * W3s[2 * n1 + 1];
            }
#pragma unroll
            for (int off = 1; off <= 2; off <<= 1) {
                sa0 += __shfl_xor_sync(0xffffffffu, sa0, off);
                sa1 += __shfl_xor_sync(0xffffffffu, sa1, off);
                sb0 += __shfl_xor_sync(0xffffffffu, sb0, off);
                sb1 += __shfl_xor_sync(0xffffffffu, sb1, off);
            }
            if (tig == 0) {
#pragma unroll
                for (int half = 0; half < 2; half++) {
                    int row = w * 32 + mt * 16 + gid + half * 8;
                    float o0 = (half ? sb0 : sa0) + b30;
                    float o1 = (half ? sb1 : sa1) + b31;
                    int pp = base + row;
                    int g2 = pp / PTS_PER_G;
                    size_t bofs = (size_t)pp + (size_t)g2 * PTS_PER_G;
                    g_bias[bofs] = o0;
                    g_bias[bofs + PTS_PER_G] = o1;
                }
            }
        }
        __syncthreads();
    }
}

// ---------------- fused sim + bias + softmax + out ----------------
__global__ void attn_kernel() {
    const int h = blockIdx.y;
    const int i0 = blockIdx.x * 32;
    __shared__ float qs[32][65];
    __shared__ float4 ps4[32][37];
    __shared__ float rsum[32];
    const int tid = threadIdx.x;

    for (int idx = tid; idx < 32 * 64; idx += 256) {
        int r = idx & 31, d = idx >> 5;
        int i = i0 + r;
        qs[r][d] = (i < NPOS) ? g_q[(size_t)(h * 64 + d) * NPOS + i] * SCALE : 0.f;
    }
    __syncthreads();

    const float4* k4 = reinterpret_cast<const float4*>(g_k + (size_t)h * 64 * JJ);
    for (int idx = tid; idx < 8 * 36; idx += 256) {
        int rg = idx / 36, j4 = idx - rg * 36;
        float4 s0 = {0, 0, 0, 0}, s1 = {0, 0, 0, 0}, s2 = {0, 0, 0, 0}, s3 = {0, 0, 0, 0};
#pragma unroll 16
        for (int d = 0; d < 64; d++) {
            float4 kv = k4[d * 36 + j4];
            float q0 = qs[rg * 4 + 0][d], q1 = qs[rg * 4 + 1][d];
            float q2 = qs[rg * 4 + 2][d], q3 = qs[rg * 4 + 3][d];
            s0.x = fmaf(q0, kv.x, s0.x); s0.y = fmaf(q0, kv.y, s0.y);
            s0.z = fmaf(q0, kv.z, s0.z); s0.w = fmaf(q0, kv.w, s0.w);
            s1.x = fmaf(q1, kv.x, s1.x); s1.y = fmaf(q1, kv.y, s1.y);
            s1.z = fmaf(q1, kv.z, s1.z); s1.w = fmaf(q1, kv.w, s1.w);
            s2.x = fmaf(q2, kv.x, s2.x); s2.y = fmaf(q2, kv.y, s2.y);
            s2.z = fmaf(q2, kv.z, s2.z); s2.w = fmaf(q2, kv.w, s2.w);
            s3.x = fmaf(q3, kv.x, s3.x); s3.y = fmaf(q3, kv.y, s3.y);
            s3.z = fmaf(q3, kv.z, s3.z); s3.w = fmaf(q3, kv.w, s3.w);
        }
        float4 sv[4] = {s0, s1, s2, s3};
#pragma unroll
        for (int u = 0; u < 4; u++) {
            int r = rg * 4 + u, i = i0 + r;
            if (i < NPOS) {
                const float4 b = *reinterpret_cast<const float4*>(
                    &g_bias[((size_t)h * NPOS + i) * JJ + 4 * j4]);
                sv[u].x += b.x; sv[u].y += b.y; sv[u].z += b.z; sv[u].w += b.w;
            }
            ps4[r][j4] = sv[u];
        }
    }
    __syncthreads();

    float* ps = reinterpret_cast<float*>(ps4);
    const int w = tid >> 5, lane = tid & 31;
#pragma unroll
    for (int rr = 0; rr < 4; rr++) {
        int row = w + rr * 8;
        float* pr = ps + row * 148;
        float m = -1e30f;
        for (int j = lane; j < JJ; j += 32) m = fmaxf(m, pr[j]);
#pragma unroll
        for (int o = 16; o; o >>= 1) m = fmaxf(m, __shfl_xor_sync(0xffffffffu, m, o));
        float s = 0.f;
        for (int j = lane; j < JJ; j += 32) {
            float e = fast_exp(pr[j] - m);
            pr[j] = e;
            s += e;
        }
#pragma unroll
        for (int o = 16; o; o >>= 1) s += __shfl_xor_sync(0xffffffffu, s, o);
        if (lane == 0) rsum[row] = s;
    }
    __syncthreads();

    const float4* v4 = reinterpret_cast<const float4*>(g_v + (size_t)h * 64 * JJ);
    for (int idx = tid; idx < 16 * 32; idx += 256) {
        int dg = idx >> 5, r = idx & 31;
        int i = i0 + r;
        if (i >= NPOS) continue;
        float o0 = 0.f, o1 = 0.f, o2 = 0.f, o3 = 0.f;
#pragma unroll 4
        for (int j4 = 0; j4 < 36; j4++) {
            float4 pv = ps4[r][j4];
            float4 v0 = v4[(dg * 4 + 0) * 36 + j4];
            float4 v1 = v4[(dg * 4 + 1) * 36 + j4];
            float4 v2 = v4[(dg * 4 + 2) * 36 + j4];
            float4 v3 = v4[(dg * 4 + 3) * 36 + j4];
            o0 += pv.x * v0.x + pv.y * v0.y + pv.z * v0.z + pv.w * v0.w;
            o1 += pv.x * v1.x + pv.y * v1.y + pv.z * v1.z + pv.w * v1.w;
            o2 += pv.x * v2.x + pv.y * v2.y + pv.z * v2.z + pv.w * v2.w;
            o3 += pv.x * v3.x + pv.y * v3.y + pv.z * v3.z + pv.w * v3.w;
        }
        float inv = 1.0f / rsum[r];
        g_ao[(size_t)(h * 64 + dg * 4 + 0) * NPOS + i] = o0 * inv;
        g_ao[(size_t)(h * 64 + dg * 4 + 1) * NPOS + i] = o1 * inv;
        g_ao[(size_t)(h * 64 + dg * 4 + 2) * NPOS + i] = o2 * inv;
        g_ao[(size_t)(h * 64 + dg * 4 + 3) * NPOS + i] = o3 * inv;
    }
}

// ---------------- launcher ----------------
extern "C" void kernel_launch(void* const* d_in, const int* in_sizes, int n_in,
                              void* d_out, int out_size) {
    const float* x1    = (const float*)d_in[0];
    const float* x2    = (const float*)d_in[1];
    const float* w_off1= (const float*)d_in[2];
    const float* b_off1= (const float*)d_in[3];
    const float* w_off2= (const float*)d_in[4];
    const float* wq    = (const float*)d_in[5];
    const float* wk    = (const float*)d_in[6];
    const float* wv    = (const float*)d_in[7];
    const float* wout  = (const float*)d_in[8];
    const float* bout  = (const float*)d_in[9];
    const float* cpb_w1= (const float*)d_in[10];
    const float* cpb_b1= (const float*)d_in[11];
    const float* cpb_w2= (const float*)d_in[12];
    const float* cpb_b2= (const float*)d_in[13];
    const float* cpb_w3= (const float*)d_in[14];
    const float* cpb_b3= (const float*)d_in[15];
    float* out = (float*)d_out;

    float *qp, *kvp, *kp, *vp, *aop;
    cudaGetSymbolAddress((void**)&qp,  g_q);
    cudaGetSymbolAddress((void**)&kvp, g_kv);
    cudaGetSymbolAddress((void**)&kp,  g_k);
    cudaGetSymbolAddress((void**)&vp,  g_v);
    cudaGetSymbolAddress((void**)&aop, g_ao);

    // 1) q = wq @ f1
    tf32gemm<<<dim3(40, 8, 1), 256>>>(wq, x1, qp, INNER, NPOS, DIM, SEQ, 1, NPOS, 0,
                                      nullptr, nullptr, nullptr);

    // 2) depthwise conv + gelu (+ cls copy)
    dconv_kernel<<<INNER, JJ>>>(w_off1, b_off1, x1, out);

    // 3) 1x1 conv + tanh + grid
    offgrid_kernel<<<G, JJ>>>(w_off2);

    // 4) bilinear sample
    gsample_kernel<<<G * JJ, 64>>>(x2);

    // 5) k, v GEMMs in one launch (z selects weights/output)
    tf32gemm<<<dim3(3, 8, 2), 256>>>(wk, kvp, kp, INNER, JJ, DIM, JJ, 0, JJ, 0,
                                     nullptr, wv, vp);

    // 6) CPB bias MLP
    cpb_mma_kernel<<<CPB_BLOCKS, 128>>>(cpb_w1, cpb_b1, cpb_w2, cpb_b2,
                                        cpb_w3, cpb_b3);

    // 7) attention
    attn_kernel<<<dim3((NPOS + 31) / 32, HEADS), 256>>>();

    // 8) wout @ attn_out + bout
    tf32gemm<<<dim3(40, 4, 1), 256>>>(wout, aop, out, DIM, NPOS, INNER, NPOS, 0, SEQ, 1,
                                      bout, nullptr, nullptr);
}